// round 3
// baseline (speedup 1.0000x reference)
#include <cuda_runtime.h>
#include <math.h>
#include <stdint.h>

#define Bsz 8
#define Sq  512
#define Dm  512
#define Hh  8
#define DK  64
#define FF  2048
#define MTOK (Bsz*Sq)   // 4096
#define NCPT 1000
#define NBH (Bsz*Hh)    // 64

// ---------------- scratch (device globals; no allocation) ----------------
__device__ float g_x0[MTOK*Dm];
__device__ float g_y [MTOK*Dm];
__device__ float g_x [MTOK*Dm];
__device__ float g_Q [MTOK*Dm];
__device__ float g_K [MTOK*Dm];
__device__ float g_V [MTOK*Dm];
__device__ float g_A [MTOK*Dm];
__device__ float g_O [MTOK*Dm];
__device__ float g_T1[MTOK*Dm];
__device__ float g_Hf[MTOK*FF];
__device__ float g_Cc[MTOK*2*Dm];
__device__ float g_M1[MTOK*512];
__device__ float g_M2[MTOK*1024];
__device__ float g_S [NBH*Sq*Sq];   // 64 MB score/attn-weight scratch

// ---------------- embed ----------------
__global__ void embed_kernel(const int* __restrict__ c_data, const int* __restrict__ ca_data,
                             const float* __restrict__ c_emb, const float* __restrict__ ca_emb,
                             float* __restrict__ x0, float* __restrict__ y, float* __restrict__ x)
{
    int r = blockIdx.x;
    int c = c_data[r];
    int resp = (ca_data[r] - c) / NCPT;
    const float* er = c_emb + (size_t)c * Dm;
    const float* ar = ca_emb + (size_t)resp * Dm;
    for (int j = threadIdx.x; j < Dm; j += blockDim.x) {
        float v = er[j];
        x0[(size_t)r*Dm + j] = v;
        x [(size_t)r*Dm + j] = v;
        y [(size_t)r*Dm + j] = v + ar[j];
    }
}

// ---------------- tf32 helpers ----------------
__device__ __forceinline__ void split_tf32(float x, float& hi, float& lo) {
    uint32_t u;
    asm("cvt.rna.tf32.f32 %0, %1;" : "=r"(u) : "f"(x));
    hi = __uint_as_float(u);
    float r = x - hi;
    uint32_t v;
    asm("cvt.rna.tf32.f32 %0, %1;" : "=r"(v) : "f"(r));
    lo = __uint_as_float(v);
}
__device__ __forceinline__ void mma_tf32(float* c, const uint32_t* a, const uint32_t* b) {
    asm volatile(
        "mma.sync.aligned.m16n8k8.row.col.f32.tf32.tf32.f32 "
        "{%0,%1,%2,%3}, {%4,%5,%6,%7}, {%8,%9}, {%0,%1,%2,%3};"
        : "+f"(c[0]), "+f"(c[1]), "+f"(c[2]), "+f"(c[3])
        : "r"(a[0]), "r"(a[1]), "r"(a[2]), "r"(a[3]), "r"(b[0]), "r"(b[1]));
}

// ---------------- tensor-core GEMM: C = A[MxK] @ W[KxN] + bias (3xTF32) -----
#define BM 128
#define BN 128
#define BK 16
#define PAD 8
#define LDAS (BM + PAD)   // 136 -> conflict-free fragment loads

__global__ __launch_bounds__(256)
void gemm_tc(const float* __restrict__ A, const float* __restrict__ W,
             const float* __restrict__ bias, float* __restrict__ C,
             int M, int N, int K, int relu)
{
    __shared__ float Ah[2][BK][LDAS];
    __shared__ float Al[2][BK][LDAS];
    __shared__ float Bh[2][BK][LDAS];
    __shared__ float Bl[2][BK][LDAS];

    int tid = threadIdx.x;
    int row0 = blockIdx.y * BM, col0 = blockIdx.x * BN;

    int warp = tid >> 5, lane = tid & 31;
    int wm = warp & 3, wn = warp >> 2;          // 4 x 2 warp grid
    int g = lane >> 2, tig = lane & 3;

    // global load mapping
    int arow = tid >> 1, akc = (tid & 1) * 8;   // A: 128 rows x 16 k
    int bkr = tid >> 4, bcol = (tid & 15) * 8;  // B: 16 k x 128 n
    const float* Ap = A + (size_t)(row0 + arow) * K + akc;
    int bcg = col0 + bcol;

    float acc[2][8][4];
#pragma unroll
    for (int i = 0; i < 2; i++)
#pragma unroll
        for (int j = 0; j < 8; j++)
#pragma unroll
            for (int q = 0; q < 4; q++) acc[i][j][q] = 0.f;

    float ra[8], rb[8];
    int T = K / BK;

    // prefetch chunk 0
    {
        float4 a0 = *(const float4*)(Ap);
        float4 a1 = *(const float4*)(Ap + 4);
        ra[0]=a0.x; ra[1]=a0.y; ra[2]=a0.z; ra[3]=a0.w;
        ra[4]=a1.x; ra[5]=a1.y; ra[6]=a1.z; ra[7]=a1.w;
        const float* Wp = W + (size_t)bkr * N + bcg;
#pragma unroll
        for (int j = 0; j < 8; j++) rb[j] = (bcg + j < N) ? Wp[j] : 0.f;
    }
    {
#pragma unroll
        for (int j = 0; j < 8; j++) {
            float h, l; split_tf32(ra[j], h, l);
            Ah[0][akc + j][arow] = h; Al[0][akc + j][arow] = l;
        }
#pragma unroll
        for (int j = 0; j < 8; j++) {
            float h, l; split_tf32(rb[j], h, l);
            Bh[0][bkr][bcol + j] = h; Bl[0][bkr][bcol + j] = l;
        }
    }
    __syncthreads();

    int buf = 0;
    for (int t = 0; t < T; t++) {
        if (t + 1 < T) {
            const float* Ap2 = Ap + (t + 1) * BK;
            float4 a0 = *(const float4*)(Ap2);
            float4 a1 = *(const float4*)(Ap2 + 4);
            ra[0]=a0.x; ra[1]=a0.y; ra[2]=a0.z; ra[3]=a0.w;
            ra[4]=a1.x; ra[5]=a1.y; ra[6]=a1.z; ra[7]=a1.w;
            const float* Wp = W + (size_t)((t + 1) * BK + bkr) * N + bcg;
#pragma unroll
            for (int j = 0; j < 8; j++) rb[j] = (bcg + j < N) ? Wp[j] : 0.f;
        }
#pragma unroll
        for (int ks = 0; ks < 2; ks++) {
            int kk = ks * 8;
            uint32_t ah[2][4], al[2][4];
#pragma unroll
            for (int mt = 0; mt < 2; mt++) {
                int m0 = wm * 32 + mt * 16 + g;
                ah[mt][0] = __float_as_uint(Ah[buf][kk + tig    ][m0]);
                ah[mt][1] = __float_as_uint(Ah[buf][kk + tig    ][m0 + 8]);
                ah[mt][2] = __float_as_uint(Ah[buf][kk + tig + 4][m0]);
                ah[mt][3] = __float_as_uint(Ah[buf][kk + tig + 4][m0 + 8]);
                al[mt][0] = __float_as_uint(Al[buf][kk + tig    ][m0]);
                al[mt][1] = __float_as_uint(Al[buf][kk + tig    ][m0 + 8]);
                al[mt][2] = __float_as_uint(Al[buf][kk + tig + 4][m0]);
                al[mt][3] = __float_as_uint(Al[buf][kk + tig + 4][m0 + 8]);
            }
#pragma unroll
            for (int nt = 0; nt < 8; nt++) {
                int n0 = wn * 64 + nt * 8 + g;
                uint32_t bh[2], bl[2];
                bh[0] = __float_as_uint(Bh[buf][kk + tig    ][n0]);
                bh[1] = __float_as_uint(Bh[buf][kk + tig + 4][n0]);
                bl[0] = __float_as_uint(Bl[buf][kk + tig    ][n0]);
                bl[1] = __float_as_uint(Bl[buf][kk + tig + 4][n0]);
#pragma unroll
                for (int mt = 0; mt < 2; mt++) {
                    mma_tf32(acc[mt][nt], ah[mt], bh);
                    mma_tf32(acc[mt][nt], al[mt], bh);
                    mma_tf32(acc[mt][nt], ah[mt], bl);
                }
            }
        }
        if (t + 1 < T) {
            int nb = buf ^ 1;
#pragma unroll
            for (int j = 0; j < 8; j++) {
                float h, l; split_tf32(ra[j], h, l);
                Ah[nb][akc + j][arow] = h; Al[nb][akc + j][arow] = l;
            }
#pragma unroll
            for (int j = 0; j < 8; j++) {
                float h, l; split_tf32(rb[j], h, l);
                Bh[nb][bkr][bcol + j] = h; Bl[nb][bkr][bcol + j] = l;
            }
            __syncthreads();
            buf = nb;
        }
    }

    // epilogue
#pragma unroll
    for (int mt = 0; mt < 2; mt++) {
        int rbase = row0 + wm * 32 + mt * 16;
#pragma unroll
        for (int nt = 0; nt < 8; nt++) {
            int cbase = col0 + wn * 64 + nt * 8 + 2 * tig;
#pragma unroll
            for (int half = 0; half < 2; half++) {
                int r = rbase + g + half * 8;
                float v0 = acc[mt][nt][half * 2 + 0];
                float v1 = acc[mt][nt][half * 2 + 1];
                if (cbase < N) {
                    float o0 = v0 + bias[cbase];
                    if (relu) o0 = fmaxf(o0, 0.f);
                    C[(size_t)r * N + cbase] = o0;
                }
                if (cbase + 1 < N) {
                    float o1 = v1 + bias[cbase + 1];
                    if (relu) o1 = fmaxf(o1, 0.f);
                    C[(size_t)r * N + cbase + 1] = o1;
                }
            }
        }
    }
}

// ---------------- attention part 1: scores (lower-tri tiles) ----------------
__global__ __launch_bounds__(256)
void score_kernel(const float* __restrict__ Q, const float* __restrict__ Kp,
                  float* __restrict__ S)
{
    int bx = blockIdx.x, by = blockIdx.y;
    if (bx > by) return;                 // fully masked tile
    int z = blockIdx.z;
    int b = z >> 3, h = z & 7;
    __shared__ float Qs[64][68];         // [d][q]
    __shared__ float Ks[64][68];         // [d][k]
    int tid = threadIdx.x;
    const float* Qbase = Q  + ((size_t)(b * Sq + by * 64)) * Dm + h * DK;
    const float* Kbase = Kp + ((size_t)(b * Sq + bx * 64)) * Dm + h * DK;
#pragma unroll
    for (int l = 0; l < 4; l++) {
        int idx = tid + l * 256;
        int r = idx >> 4, c4 = (idx & 15) * 4;
        float4 q4 = *(const float4*)(Qbase + (size_t)r * Dm + c4);
        Qs[c4 + 0][r] = q4.x; Qs[c4 + 1][r] = q4.y;
        Qs[c4 + 2][r] = q4.z; Qs[c4 + 3][r] = q4.w;
        float4 k4 = *(const float4*)(Kbase + (size_t)r * Dm + c4);
        Ks[c4 + 0][r] = k4.x; Ks[c4 + 1][r] = k4.y;
        Ks[c4 + 2][r] = k4.z; Ks[c4 + 3][r] = k4.w;
    }
    __syncthreads();
    int tx = tid & 15, ty = tid >> 4;
    float acc[4][4];
#pragma unroll
    for (int i = 0; i < 4; i++)
#pragma unroll
        for (int j = 0; j < 4; j++) acc[i][j] = 0.f;
#pragma unroll 8
    for (int d = 0; d < 64; d++) {
        float4 a4 = *(const float4*)&Qs[d][ty * 4];
        float4 b4 = *(const float4*)&Ks[d][tx * 4];
        float a[4] = {a4.x, a4.y, a4.z, a4.w};
        float b[4] = {b4.x, b4.y, b4.z, b4.w};
#pragma unroll
        for (int i = 0; i < 4; i++)
#pragma unroll
            for (int j = 0; j < 4; j++) acc[i][j] = fmaf(a[i], b[j], acc[i][j]);
    }
    float* Srow = S + ((size_t)z * Sq + by * 64) * Sq + bx * 64;
#pragma unroll
    for (int i = 0; i < 4; i++)
#pragma unroll
        for (int j = 0; j < 4; j++)
            Srow[(size_t)(ty * 4 + i) * Sq + tx * 4 + j] = acc[i][j] * 0.125f;
}

// ---------------- block reduce helpers (256 threads) ----------------
__device__ __forceinline__ float brmax(float v, float* red) {
    int tid = threadIdx.x;
    red[tid] = v; __syncthreads();
#pragma unroll
    for (int s = 128; s > 0; s >>= 1) {
        if (tid < s) red[tid] = fmaxf(red[tid], red[tid + s]);
        __syncthreads();
    }
    float r = red[0]; __syncthreads(); return r;
}
__device__ __forceinline__ float brsum(float v, float* red) {
    int tid = threadIdx.x;
    red[tid] = v; __syncthreads();
#pragma unroll
    for (int s = 128; s > 0; s >>= 1) {
        if (tid < s) red[tid] += red[tid + s];
        __syncthreads();
    }
    float r = red[0]; __syncthreads(); return r;
}

// ---------------- attention part 2: per-row softmax/cumsum/decay/softmax ------
__global__ __launch_bounds__(256)
void decay_softmax_kernel(float* __restrict__ S, const float* __restrict__ gammas,
                          int layer, int strict)
{
    __shared__ float sc[Sq];
    __shared__ float pa[Sq];
    __shared__ float red[256];
    int i = blockIdx.x, z = blockIdx.y;
    int h = z & 7;
    int tid = threadIdx.x;
    float* row = S + ((size_t)z * Sq + i) * Sq;
    int kmax = i - strict;
    if (kmax < 0) {
        for (int k = tid; k < Sq; k += 256) row[k] = 0.f;
        return;
    }
    for (int k = tid; k < Sq; k += 256) sc[k] = row[k];
    __syncthreads();

    // softmax #1 -> p
    float lm = -3e38f;
    for (int k = tid; k < Sq; k += 256) if (k <= kmax) lm = fmaxf(lm, sc[k]);
    float m1 = brmax(lm, red);
    float ls = 0.f;
    for (int k = tid; k < Sq; k += 256) {
        float p = (k <= kmax) ? expf(sc[k] - m1) : 0.f;
        pa[k] = p; ls += p;
    }
    float inv1 = 1.f / brsum(ls, red);
    for (int k = tid; k < Sq; k += 256) pa[k] *= inv1;
    __syncthreads();

    // inclusive cumsum of p (Hillis-Steele, 512 elems / 256 threads)
    for (int off = 1; off < Sq; off <<= 1) {
        int i1 = tid + 256;
        float a0 = (tid >= off) ? pa[tid - off] : 0.f;
        float a1 = (i1  >= off) ? pa[i1  - off] : 0.f;
        __syncthreads();
        pa[tid] += a0; pa[i1] += a1;
        __syncthreads();
    }
    float total = pa[Sq - 1];

    float gm = gammas[layer * Hh + h];
    float sp = (gm > 20.f) ? gm : log1pf(expf(gm));
    float gamma = -sp;

    for (int k = tid; k < Sq; k += 256) {
        if (k <= kmax) {
            float suf  = total - pa[k];
            float pos  = (float)(i - k);
            float dist = sqrtf(fmaxf(suf * pos, 0.f));
            float te   = expf(dist * gamma);
            te = fminf(fmaxf(te, 1e-5f), 1e5f);
            sc[k] = sc[k] * te;
        }
    }
    __syncthreads();

    // softmax #2 -> attn weights
    lm = -3e38f;
    for (int k = tid; k < Sq; k += 256) if (k <= kmax) lm = fmaxf(lm, sc[k]);
    float m2 = brmax(lm, red);
    ls = 0.f;
    for (int k = tid; k < Sq; k += 256) {
        float p = (k <= kmax) ? expf(sc[k] - m2) : 0.f;
        pa[k] = p; ls += p;
    }
    float inv2 = 1.f / brsum(ls, red);
    for (int k = tid; k < Sq; k += 256) row[k] = (k <= kmax) ? pa[k] * inv2 : 0.f;
}

// ---------------- attention part 3: O = P @ V ----------------
__global__ __launch_bounds__(256)
void av_kernel(const float* __restrict__ S, const float* __restrict__ V,
               float* __restrict__ O)
{
    int qt = blockIdx.x, z = blockIdx.y;
    int b = z >> 3, h = z & 7;
    __shared__ float Ps[16][68];   // [k][q]
    __shared__ float Vs[16][68];   // [k][d]
    int tid = threadIdx.x, tx = tid & 15, ty = tid >> 4;
    float acc[4][4];
#pragma unroll
    for (int i = 0; i < 4; i++)
#pragma unroll
        for (int j = 0; j < 4; j++) acc[i][j] = 0.f;

    const float* Srow  = S + ((size_t)z * Sq + qt * 64) * Sq;
    const float* Vbase = V + ((size_t)b * Sq) * Dm + h * DK;
    int nkt = qt * 4 + 4;            // P[q][k]=0 for k>q -> skip upper tiles
    for (int kt = 0; kt < nkt; kt++) {
        int k0 = kt * 16;
        {
            int q = tid >> 2, kc = (tid & 3) * 4;
            float4 p4 = *(const float4*)(Srow + (size_t)q * Sq + k0 + kc);
            Ps[kc + 0][q] = p4.x; Ps[kc + 1][q] = p4.y;
            Ps[kc + 2][q] = p4.z; Ps[kc + 3][q] = p4.w;
            int kr = tid >> 4, d4 = (tid & 15) * 4;
            *(float4*)&Vs[kr][d4] = *(const float4*)(Vbase + (size_t)(k0 + kr) * Dm + d4);
        }
        __syncthreads();
#pragma unroll
        for (int kk = 0; kk < 16; kk++) {
            float4 a4 = *(const float4*)&Ps[kk][ty * 4];
            float4 b4 = *(const float4*)&Vs[kk][tx * 4];
            float a[4] = {a4.x, a4.y, a4.z, a4.w};
            float b[4] = {b4.x, b4.y, b4.z, b4.w};
#pragma unroll
            for (int i = 0; i < 4; i++)
#pragma unroll
                for (int j = 0; j < 4; j++) acc[i][j] = fmaf(a[i], b[j], acc[i][j]);
        }
        __syncthreads();
    }
    float* Orow = O + ((size_t)(b * Sq + qt * 64)) * Dm + h * DK;
#pragma unroll
    for (int i = 0; i < 4; i++)
#pragma unroll
        for (int j = 0; j < 4; j++)
            Orow[(size_t)(ty * 4 + i) * Dm + tx * 4 + j] = acc[i][j];
}

// ---------------- residual + LayerNorm: out = LN(A + B) ----------------
__global__ void ln_add_kernel(const float* __restrict__ A, const float* __restrict__ Bv,
                              const float* __restrict__ sc, const float* __restrict__ bi,
                              float* __restrict__ out)
{
    int r = blockIdx.x, tid = threadIdx.x;
    const float* a  = A  + (size_t)r * Dm;
    const float* bq = Bv + (size_t)r * Dm;
    float v[4];
    float s = 0.f, s2 = 0.f;
#pragma unroll
    for (int j = 0; j < 4; j++) {
        int c = tid + j * 128;
        float t = a[c] + bq[c];
        v[j] = t; s += t; s2 += t * t;
    }
    __shared__ float rs[4], rs2[4];
#pragma unroll
    for (int o = 16; o > 0; o >>= 1) {
        s  += __shfl_down_sync(0xffffffffu, s,  o);
        s2 += __shfl_down_sync(0xffffffffu, s2, o);
    }
    int w = tid >> 5, l = tid & 31;
    if (l == 0) { rs[w] = s; rs2[w] = s2; }
    __syncthreads();
    float ss  = rs[0] + rs[1] + rs[2] + rs[3];
    float ss2 = rs2[0] + rs2[1] + rs2[2] + rs2[3];
    float mean = ss / 512.f;
    float var  = ss2 / 512.f - mean * mean;
    float rstd = rsqrtf(var + 1e-5f);
#pragma unroll
    for (int j = 0; j < 4; j++) {
        int c = tid + j * 128;
        out[(size_t)r * Dm + c] = (v[j] - mean) * rstd * sc[c] + bi[c];
    }
}

// ---------------- concat [x, x0] ----------------
__global__ void concat_kernel(const float* __restrict__ x, const float* __restrict__ x0,
                              float* __restrict__ out)
{
    int r = blockIdx.x;
    for (int j = threadIdx.x; j < 2 * Dm; j += blockDim.x)
        out[(size_t)r * 2 * Dm + j] = (j < Dm) ? x[(size_t)r*Dm + j]
                                               : x0[(size_t)r*Dm + j - Dm];
}

// ---------------- host ----------------
static inline void gemm(const float* A, const float* W, const float* bias,
                        float* C, int M, int N, int K, int relu)
{
    dim3 grid((N + 127) / 128, M / 128);
    gemm_tc<<<grid, 256>>>(A, W, bias, C, M, N, K, relu);
}

extern "C" void kernel_launch(void* const* d_in, const int* in_sizes, int n_in,
                              void* d_out, int out_size)
{
    const int*   c_data  = (const int*)  d_in[0];
    const int*   ca_data = (const int*)  d_in[1];
    const float* c_emb   = (const float*)d_in[2];
    const float* ca_emb  = (const float*)d_in[3];
    const float* Wk      = (const float*)d_in[4];
    const float* bk      = (const float*)d_in[5];
    const float* Wv      = (const float*)d_in[6];
    const float* bv      = (const float*)d_in[7];
    const float* Wo      = (const float*)d_in[8];
    const float* bo      = (const float*)d_in[9];
    const float* gammas  = (const float*)d_in[10];
    const float* ln1s    = (const float*)d_in[11];
    const float* ln1b    = (const float*)d_in[12];
    const float* W1      = (const float*)d_in[13];
    const float* b1      = (const float*)d_in[14];
    const float* W2      = (const float*)d_in[15];
    const float* b2      = (const float*)d_in[16];
    const float* ln2s    = (const float*)d_in[17];
    const float* ln2b    = (const float*)d_in[18];
    const float* oW0     = (const float*)d_in[19];
    const float* ob0     = (const float*)d_in[20];
    const float* oW1     = (const float*)d_in[21];
    const float* ob1     = (const float*)d_in[22];
    const float* oW2     = (const float*)d_in[23];
    const float* ob2     = (const float*)d_in[24];
    float* out = (float*)d_out;

    float *x0, *y, *x, *Qb, *Kb, *Vb, *Ab, *Ob, *T1, *Hf, *Cc, *M1, *M2, *Sb;
    cudaGetSymbolAddress((void**)&x0, g_x0);
    cudaGetSymbolAddress((void**)&y,  g_y);
    cudaGetSymbolAddress((void**)&x,  g_x);
    cudaGetSymbolAddress((void**)&Qb, g_Q);
    cudaGetSymbolAddress((void**)&Kb, g_K);
    cudaGetSymbolAddress((void**)&Vb, g_V);
    cudaGetSymbolAddress((void**)&Ab, g_A);
    cudaGetSymbolAddress((void**)&Ob, g_O);
    cudaGetSymbolAddress((void**)&T1, g_T1);
    cudaGetSymbolAddress((void**)&Hf, g_Hf);
    cudaGetSymbolAddress((void**)&Cc, g_Cc);
    cudaGetSymbolAddress((void**)&M1, g_M1);
    cudaGetSymbolAddress((void**)&M2, g_M2);
    cudaGetSymbolAddress((void**)&Sb, g_S);

    embed_kernel<<<MTOK, 128>>>(c_data, ca_data, c_emb, ca_emb, x0, y, x);

    for (int li = 0; li < 6; li++) {
        int strict, ap;
        float* qio; const float *kin, *vin;
        if (li < 2)            { strict = 0; ap = 1; qio = y; kin = x0; vin = y; }
        else {
            int j = li - 2;
            if ((j & 1) == 0)  { strict = 0; ap = 0; qio = x; kin = x;  vin = x; }
            else               { strict = 1; ap = 1; qio = x; kin = x;  vin = y; }
        }
        const float* Wk_i = Wk + (size_t)li * Dm * Dm;  const float* bk_i = bk + li * Dm;
        const float* Wv_i = Wv + (size_t)li * Dm * Dm;  const float* bv_i = bv + li * Dm;
        const float* Wo_i = Wo + (size_t)li * Dm * Dm;  const float* bo_i = bo + li * Dm;

        gemm(qio, Wk_i, bk_i, Qb, MTOK, Dm, Dm, 0);
        const float* Kuse;
        if (kin == qio) Kuse = Qb;
        else { gemm(kin, Wk_i, bk_i, Kb, MTOK, Dm, Dm, 0); Kuse = Kb; }
        gemm(vin, Wv_i, bv_i, Vb, MTOK, Dm, Dm, 0);

        score_kernel<<<dim3(8, 8, NBH), 256>>>(Qb, Kuse, Sb);
        decay_softmax_kernel<<<dim3(Sq, NBH), 256>>>(Sb, gammas, li, strict);
        av_kernel<<<dim3(8, NBH), 256>>>(Sb, Vb, Ab);

        gemm(Ab, Wo_i, bo_i, Ob, MTOK, Dm, Dm, 0);
        ln_add_kernel<<<MTOK, 128>>>(qio, Ob, ln1s + li*Dm, ln1b + li*Dm, ap ? T1 : qio);
        if (ap) {
            gemm(T1, W1 + (size_t)li * Dm * FF, b1 + li * FF, Hf, MTOK, FF, Dm, 1);
            gemm(Hf, W2 + (size_t)li * FF * Dm, b2 + li * Dm, Ob, MTOK, Dm, FF, 0);
            ln_add_kernel<<<MTOK, 128>>>(T1, Ob, ln2s + li*Dm, ln2b + li*Dm, qio);
        }
    }

    concat_kernel<<<MTOK, 256>>>(x, x0, Cc);
    gemm(Cc, oW0, ob0, M1, MTOK, 512,  2 * Dm, 1);
    gemm(M1, oW1, ob1, M2, MTOK, 1024, 512,    1);
    gemm(M2, oW2, ob2, out, MTOK, NCPT, 1024,  0);
}

// round 4
// speedup vs baseline: 1.1067x; 1.1067x over previous
#include <cuda_runtime.h>
#include <math.h>
#include <stdint.h>

#define Bsz 8
#define Sq  512
#define Dm  512
#define Hh  8
#define DK  64
#define FF  2048
#define MTOK (Bsz*Sq)   // 4096
#define NCPT 1000
#define NBH (Bsz*Hh)    // 64

// ---------------- scratch (device globals; no allocation) ----------------
__device__ float g_x0[MTOK*Dm];
__device__ float g_y [MTOK*Dm];
__device__ float g_x [MTOK*Dm];
__device__ float g_Q [MTOK*Dm];
__device__ float g_K [MTOK*Dm];
__device__ float g_V [MTOK*Dm];
__device__ float g_A [MTOK*Dm];
__device__ float g_O [MTOK*Dm];
__device__ float g_T1[MTOK*Dm];
__device__ float g_Hf[MTOK*FF];
__device__ float g_Cc[MTOK*2*Dm];
__device__ float g_M1[MTOK*512];
__device__ float g_M2[MTOK*1024];
__device__ float g_S [NBH*Sq*Sq];   // 64 MB score/attn-weight scratch

// ---------------- embed ----------------
__global__ void embed_kernel(const int* __restrict__ c_data, const int* __restrict__ ca_data,
                             const float* __restrict__ c_emb, const float* __restrict__ ca_emb,
                             float* __restrict__ x0, float* __restrict__ y, float* __restrict__ x)
{
    int r = blockIdx.x;
    int c = c_data[r];
    int resp = (ca_data[r] - c) / NCPT;
    const float* er = c_emb + (size_t)c * Dm;
    const float* ar = ca_emb + (size_t)resp * Dm;
    for (int j = threadIdx.x; j < Dm; j += blockDim.x) {
        float v = er[j];
        x0[(size_t)r*Dm + j] = v;
        x [(size_t)r*Dm + j] = v;
        y [(size_t)r*Dm + j] = v + ar[j];
    }
}

// ---------------- tf32 helpers ----------------
__device__ __forceinline__ void split_tf32(float x, float& hi, float& lo) {
    uint32_t u;
    asm("cvt.rna.tf32.f32 %0, %1;" : "=r"(u) : "f"(x));
    hi = __uint_as_float(u);
    float r = x - hi;
    uint32_t v;
    asm("cvt.rna.tf32.f32 %0, %1;" : "=r"(v) : "f"(r));
    lo = __uint_as_float(v);
}
__device__ __forceinline__ void mma_tf32(float* c, const uint32_t* a, const uint32_t* b) {
    asm volatile(
        "mma.sync.aligned.m16n8k8.row.col.f32.tf32.tf32.f32 "
        "{%0,%1,%2,%3}, {%4,%5,%6,%7}, {%8,%9}, {%0,%1,%2,%3};"
        : "+f"(c[0]), "+f"(c[1]), "+f"(c[2]), "+f"(c[3])
        : "r"(a[0]), "r"(a[1]), "r"(a[2]), "r"(a[3]), "r"(b[0]), "r"(b[1]));
}

// ---------------- tensor-core GEMM (3xTF32), vectorized fragment layout -----
// SMEM layout: per (ks,tig) block of 130 float4 units; unit m (or n) holds
// (hi(k), hi(k+4), lo(k), lo(k+4)) with k = ks*8 + tig — one LDS.128 per
// fragment pair, conflict-free (unit addr mod 8 = 2*tig + g).
#define BM 128
#define BN 128
#define BK 16
#define UPAD 130

__global__ __launch_bounds__(256)
void gemm_tc(const float* __restrict__ A, const float* __restrict__ W,
             const float* __restrict__ bias, float* __restrict__ C,
             int M, int N, int K, int relu)
{
    __shared__ float4 As[2][8][UPAD];
    __shared__ float4 Bs[2][8][UPAD];

    int tid = threadIdx.x;
    int row0 = blockIdx.y * BM, col0 = blockIdx.x * BN;

    int warp = tid >> 5, lane = tid & 31;
    int wm = warp & 3, wn = warp >> 2;          // 4 x 2 warp grid, 32m x 64n tiles
    int g = lane >> 2, tig = lane & 3;

    // A global mapping: thread -> (row, k-half)
    int arow = tid >> 1, aks = tid & 1;
    const float* Ap = A + (size_t)(row0 + arow) * K + aks * 8;
    // B global mapping: thread -> (col, k-half); coalesced per warp
    int bn = tid & 127, bks = tid >> 7;
    int bcg = col0 + bn;
    bool bok = (bcg < N);

    float acc[2][8][4];
#pragma unroll
    for (int i = 0; i < 2; i++)
#pragma unroll
        for (int j = 0; j < 8; j++)
#pragma unroll
            for (int q = 0; q < 4; q++) acc[i][j][q] = 0.f;

    float ra[8], rb[8];
    int T = K / BK;

    // ---- load chunk t into registers ----
    auto ldg = [&](int t) {
        float4 a0 = *(const float4*)(Ap + t * BK);
        float4 a1 = *(const float4*)(Ap + t * BK + 4);
        ra[0]=a0.x; ra[1]=a0.y; ra[2]=a0.z; ra[3]=a0.w;
        ra[4]=a1.x; ra[5]=a1.y; ra[6]=a1.z; ra[7]=a1.w;
        const float* Wp = W + (size_t)(t * BK + bks * 8) * N + bcg;
#pragma unroll
        for (int j = 0; j < 8; j++) rb[j] = bok ? Wp[(size_t)j * N] : 0.f;
    };
    // ---- split + store registers into smem buffer ----
    auto sts = [&](int bf) {
        float h[8], l[8];
#pragma unroll
        for (int j = 0; j < 8; j++) split_tf32(ra[j], h[j], l[j]);
#pragma unroll
        for (int tg = 0; tg < 4; tg++)
            As[bf][aks * 4 + tg][arow] = make_float4(h[tg], h[tg + 4], l[tg], l[tg + 4]);
#pragma unroll
        for (int j = 0; j < 8; j++) split_tf32(rb[j], h[j], l[j]);
#pragma unroll
        for (int tg = 0; tg < 4; tg++)
            Bs[bf][bks * 4 + tg][bn] = make_float4(h[tg], h[tg + 4], l[tg], l[tg + 4]);
    };

    ldg(0);
    sts(0);
    __syncthreads();

    int buf = 0;
    for (int t = 0; t < T; t++) {
        if (t + 1 < T) ldg(t + 1);
#pragma unroll
        for (int ks = 0; ks < 2; ks++) {
            int kidx = ks * 4 + tig;
            uint32_t ah[2][4], al[2][4];
#pragma unroll
            for (int mt = 0; mt < 2; mt++) {
                int r = wm * 32 + mt * 16 + g;
                float4 fa = As[buf][kidx][r];
                float4 fb = As[buf][kidx][r + 8];
                ah[mt][0] = __float_as_uint(fa.x); ah[mt][1] = __float_as_uint(fb.x);
                ah[mt][2] = __float_as_uint(fa.y); ah[mt][3] = __float_as_uint(fb.y);
                al[mt][0] = __float_as_uint(fa.z); al[mt][1] = __float_as_uint(fb.z);
                al[mt][2] = __float_as_uint(fa.w); al[mt][3] = __float_as_uint(fb.w);
            }
#pragma unroll
            for (int nt = 0; nt < 8; nt++) {
                int n0 = wn * 64 + nt * 8 + g;
                float4 f = Bs[buf][kidx][n0];
                uint32_t bh[2], bl[2];
                bh[0] = __float_as_uint(f.x); bh[1] = __float_as_uint(f.y);
                bl[0] = __float_as_uint(f.z); bl[1] = __float_as_uint(f.w);
#pragma unroll
                for (int mt = 0; mt < 2; mt++) {
                    mma_tf32(acc[mt][nt], ah[mt], bh);
                    mma_tf32(acc[mt][nt], al[mt], bh);
                    mma_tf32(acc[mt][nt], ah[mt], bl);
                }
            }
        }
        if (t + 1 < T) {
            sts(buf ^ 1);
            __syncthreads();
            buf ^= 1;
        }
    }

    // epilogue
#pragma unroll
    for (int mt = 0; mt < 2; mt++) {
        int rbase = row0 + wm * 32 + mt * 16;
#pragma unroll
        for (int nt = 0; nt < 8; nt++) {
            int cbase = col0 + wn * 64 + nt * 8 + 2 * tig;
#pragma unroll
            for (int half = 0; half < 2; half++) {
                int r = rbase + g + half * 8;
                float v0 = acc[mt][nt][half * 2 + 0];
                float v1 = acc[mt][nt][half * 2 + 1];
                if (cbase < N) {
                    float o0 = v0 + bias[cbase];
                    if (relu) o0 = fmaxf(o0, 0.f);
                    C[(size_t)r * N + cbase] = o0;
                }
                if (cbase + 1 < N) {
                    float o1 = v1 + bias[cbase + 1];
                    if (relu) o1 = fmaxf(o1, 0.f);
                    C[(size_t)r * N + cbase + 1] = o1;
                }
            }
        }
    }
}

// ---------------- attention part 1: scores (lower-tri tiles) ----------------
__global__ __launch_bounds__(256)
void score_kernel(const float* __restrict__ Q, const float* __restrict__ Kp,
                  float* __restrict__ S)
{
    int bx = blockIdx.x, by = blockIdx.y;
    if (bx > by) return;                 // fully masked tile
    int z = blockIdx.z;
    int b = z >> 3, h = z & 7;
    __shared__ float Qs[64][68];         // [d][q]
    __shared__ float Ks[64][68];         // [d][k]
    int tid = threadIdx.x;
    const float* Qbase = Q  + ((size_t)(b * Sq + by * 64)) * Dm + h * DK;
    const float* Kbase = Kp + ((size_t)(b * Sq + bx * 64)) * Dm + h * DK;
#pragma unroll
    for (int l = 0; l < 4; l++) {
        int idx = tid + l * 256;
        int r = idx >> 4, c4 = (idx & 15) * 4;
        float4 q4 = *(const float4*)(Qbase + (size_t)r * Dm + c4);
        Qs[c4 + 0][r] = q4.x; Qs[c4 + 1][r] = q4.y;
        Qs[c4 + 2][r] = q4.z; Qs[c4 + 3][r] = q4.w;
        float4 k4 = *(const float4*)(Kbase + (size_t)r * Dm + c4);
        Ks[c4 + 0][r] = k4.x; Ks[c4 + 1][r] = k4.y;
        Ks[c4 + 2][r] = k4.z; Ks[c4 + 3][r] = k4.w;
    }
    __syncthreads();
    int tx = tid & 15, ty = tid >> 4;
    float acc[4][4];
#pragma unroll
    for (int i = 0; i < 4; i++)
#pragma unroll
        for (int j = 0; j < 4; j++) acc[i][j] = 0.f;
#pragma unroll 8
    for (int d = 0; d < 64; d++) {
        float4 a4 = *(const float4*)&Qs[d][ty * 4];
        float4 b4 = *(const float4*)&Ks[d][tx * 4];
        float a[4] = {a4.x, a4.y, a4.z, a4.w};
        float b[4] = {b4.x, b4.y, b4.z, b4.w};
#pragma unroll
        for (int i = 0; i < 4; i++)
#pragma unroll
            for (int j = 0; j < 4; j++) acc[i][j] = fmaf(a[i], b[j], acc[i][j]);
    }
    float* Srow = S + ((size_t)z * Sq + by * 64) * Sq + bx * 64;
#pragma unroll
    for (int i = 0; i < 4; i++)
#pragma unroll
        for (int j = 0; j < 4; j++)
            Srow[(size_t)(ty * 4 + i) * Sq + tx * 4 + j] = acc[i][j] * 0.125f;
}

// ---------------- block reduce helpers (256 threads) ----------------
__device__ __forceinline__ float brmax(float v, float* red) {
    int tid = threadIdx.x;
    red[tid] = v; __syncthreads();
#pragma unroll
    for (int s = 128; s > 0; s >>= 1) {
        if (tid < s) red[tid] = fmaxf(red[tid], red[tid + s]);
        __syncthreads();
    }
    float r = red[0]; __syncthreads(); return r;
}
__device__ __forceinline__ float brsum(float v, float* red) {
    int tid = threadIdx.x;
    red[tid] = v; __syncthreads();
#pragma unroll
    for (int s = 128; s > 0; s >>= 1) {
        if (tid < s) red[tid] += red[tid + s];
        __syncthreads();
    }
    float r = red[0]; __syncthreads(); return r;
}

// ---------------- attention part 2: per-row softmax/cumsum/decay/softmax ------
__global__ __launch_bounds__(256)
void decay_softmax_kernel(float* __restrict__ S, const float* __restrict__ gammas,
                          int layer, int strict)
{
    __shared__ float sc[Sq];
    __shared__ float pa[Sq];
    __shared__ float red[256];
    int i = blockIdx.x, z = blockIdx.y;
    int h = z & 7;
    int tid = threadIdx.x;
    float* row = S + ((size_t)z * Sq + i) * Sq;
    int kmax = i - strict;
    if (kmax < 0) {
        for (int k = tid; k < Sq; k += 256) row[k] = 0.f;
        return;
    }
    for (int k = tid; k < Sq; k += 256) sc[k] = row[k];
    __syncthreads();

    // softmax #1 -> p
    float lm = -3e38f;
    for (int k = tid; k < Sq; k += 256) if (k <= kmax) lm = fmaxf(lm, sc[k]);
    float m1 = brmax(lm, red);
    float ls = 0.f;
    for (int k = tid; k < Sq; k += 256) {
        float p = (k <= kmax) ? expf(sc[k] - m1) : 0.f;
        pa[k] = p; ls += p;
    }
    float inv1 = 1.f / brsum(ls, red);
    for (int k = tid; k < Sq; k += 256) pa[k] *= inv1;
    __syncthreads();

    // inclusive cumsum of p (Hillis-Steele, 512 elems / 256 threads)
    for (int off = 1; off < Sq; off <<= 1) {
        int i1 = tid + 256;
        float a0 = (tid >= off) ? pa[tid - off] : 0.f;
        float a1 = (i1  >= off) ? pa[i1  - off] : 0.f;
        __syncthreads();
        pa[tid] += a0; pa[i1] += a1;
        __syncthreads();
    }
    float total = pa[Sq - 1];

    float gm = gammas[layer * Hh + h];
    float sp = (gm > 20.f) ? gm : log1pf(expf(gm));
    float gamma = -sp;

    for (int k = tid; k < Sq; k += 256) {
        if (k <= kmax) {
            float suf  = total - pa[k];
            float pos  = (float)(i - k);
            float dist = sqrtf(fmaxf(suf * pos, 0.f));
            float te   = expf(dist * gamma);
            te = fminf(fmaxf(te, 1e-5f), 1e5f);
            sc[k] = sc[k] * te;
        }
    }
    __syncthreads();

    // softmax #2 -> attn weights
    lm = -3e38f;
    for (int k = tid; k < Sq; k += 256) if (k <= kmax) lm = fmaxf(lm, sc[k]);
    float m2 = brmax(lm, red);
    ls = 0.f;
    for (int k = tid; k < Sq; k += 256) {
        float p = (k <= kmax) ? expf(sc[k] - m2) : 0.f;
        pa[k] = p; ls += p;
    }
    float inv2 = 1.f / brsum(ls, red);
    for (int k = tid; k < Sq; k += 256) row[k] = (k <= kmax) ? pa[k] * inv2 : 0.f;
}

// ---------------- attention part 3: O = P @ V ----------------
__global__ __launch_bounds__(256)
void av_kernel(const float* __restrict__ S, const float* __restrict__ V,
               float* __restrict__ O)
{
    int qt = blockIdx.x, z = blockIdx.y;
    int b = z >> 3, h = z & 7;
    __shared__ float Ps[16][68];   // [k][q]
    __shared__ float Vs[16][68];   // [k][d]
    int tid = threadIdx.x, tx = tid & 15, ty = tid >> 4;
    float acc[4][4];
#pragma unroll
    for (int i = 0; i < 4; i++)
#pragma unroll
        for (int j = 0; j < 4; j++) acc[i][j] = 0.f;

    const float* Srow  = S + ((size_t)z * Sq + qt * 64) * Sq;
    const float* Vbase = V + ((size_t)b * Sq) * Dm + h * DK;
    int nkt = qt * 4 + 4;            // P[q][k]=0 for k>q -> skip upper tiles
    for (int kt = 0; kt < nkt; kt++) {
        int k0 = kt * 16;
        {
            int q = tid >> 2, kc = (tid & 3) * 4;
            float4 p4 = *(const float4*)(Srow + (size_t)q * Sq + k0 + kc);
            Ps[kc + 0][q] = p4.x; Ps[kc + 1][q] = p4.y;
            Ps[kc + 2][q] = p4.z; Ps[kc + 3][q] = p4.w;
            int kr = tid >> 4, d4 = (tid & 15) * 4;
            *(float4*)&Vs[kr][d4] = *(const float4*)(Vbase + (size_t)(k0 + kr) * Dm + d4);
        }
        __syncthreads();
#pragma unroll
        for (int kk = 0; kk < 16; kk++) {
            float4 a4 = *(const float4*)&Ps[kk][ty * 4];
            float4 b4 = *(const float4*)&Vs[kk][tx * 4];
            float a[4] = {a4.x, a4.y, a4.z, a4.w};
            float b[4] = {b4.x, b4.y, b4.z, b4.w};
#pragma unroll
            for (int i = 0; i < 4; i++)
#pragma unroll
                for (int j = 0; j < 4; j++) acc[i][j] = fmaf(a[i], b[j], acc[i][j]);
        }
        __syncthreads();
    }
    float* Orow = O + ((size_t)(b * Sq + qt * 64)) * Dm + h * DK;
#pragma unroll
    for (int i = 0; i < 4; i++)
#pragma unroll
        for (int j = 0; j < 4; j++)
            Orow[(size_t)(ty * 4 + i) * Dm + tx * 4 + j] = acc[i][j];
}

// ---------------- residual + LayerNorm: out = LN(A + B) ----------------
__global__ void ln_add_kernel(const float* __restrict__ A, const float* __restrict__ Bv,
                              const float* __restrict__ sc, const float* __restrict__ bi,
                              float* __restrict__ out)
{
    int r = blockIdx.x, tid = threadIdx.x;
    const float* a  = A  + (size_t)r * Dm;
    const float* bq = Bv + (size_t)r * Dm;
    float v[4];
    float s = 0.f, s2 = 0.f;
#pragma unroll
    for (int j = 0; j < 4; j++) {
        int c = tid + j * 128;
        float t = a[c] + bq[c];
        v[j] = t; s += t; s2 += t * t;
    }
    __shared__ float rs[4], rs2[4];
#pragma unroll
    for (int o = 16; o > 0; o >>= 1) {
        s  += __shfl_down_sync(0xffffffffu, s,  o);
        s2 += __shfl_down_sync(0xffffffffu, s2, o);
    }
    int w = tid >> 5, l = tid & 31;
    if (l == 0) { rs[w] = s; rs2[w] = s2; }
    __syncthreads();
    float ss  = rs[0] + rs[1] + rs[2] + rs[3];
    float ss2 = rs2[0] + rs2[1] + rs2[2] + rs2[3];
    float mean = ss / 512.f;
    float var  = ss2 / 512.f - mean * mean;
    float rstd = rsqrtf(var + 1e-5f);
#pragma unroll
    for (int j = 0; j < 4; j++) {
        int c = tid + j * 128;
        out[(size_t)r * Dm + c] = (v[j] - mean) * rstd * sc[c] + bi[c];
    }
}

// ---------------- concat [x, x0] ----------------
__global__ void concat_kernel(const float* __restrict__ x, const float* __restrict__ x0,
                              float* __restrict__ out)
{
    int r = blockIdx.x;
    for (int j = threadIdx.x; j < 2 * Dm; j += blockDim.x)
        out[(size_t)r * 2 * Dm + j] = (j < Dm) ? x[(size_t)r*Dm + j]
                                               : x0[(size_t)r*Dm + j - Dm];
}

// ---------------- host ----------------
static inline void gemm(const float* A, const float* W, const float* bias,
                        float* C, int M, int N, int K, int relu)
{
    dim3 grid((N + 127) / 128, M / 128);
    gemm_tc<<<grid, 256>>>(A, W, bias, C, M, N, K, relu);
}

extern "C" void kernel_launch(void* const* d_in, const int* in_sizes, int n_in,
                              void* d_out, int out_size)
{
    const int*   c_data  = (const int*)  d_in[0];
    const int*   ca_data = (const int*)  d_in[1];
    const float* c_emb   = (const float*)d_in[2];
    const float* ca_emb  = (const float*)d_in[3];
    const float* Wk      = (const float*)d_in[4];
    const float* bk      = (const float*)d_in[5];
    const float* Wv      = (const float*)d_in[6];
    const float* bv      = (const float*)d_in[7];
    const float* Wo      = (const float*)d_in[8];
    const float* bo      = (const float*)d_in[9];
    const float* gammas  = (const float*)d_in[10];
    const float* ln1s    = (const float*)d_in[11];
    const float* ln1b    = (const float*)d_in[12];
    const float* W1      = (const float*)d_in[13];
    const float* b1      = (const float*)d_in[14];
    const float* W2      = (const float*)d_in[15];
    const float* b2      = (const float*)d_in[16];
    const float* ln2s    = (const float*)d_in[17];
    const float* ln2b    = (const float*)d_in[18];
    const float* oW0     = (const float*)d_in[19];
    const float* ob0     = (const float*)d_in[20];
    const float* oW1     = (const float*)d_in[21];
    const float* ob1     = (const float*)d_in[22];
    const float* oW2     = (const float*)d_in[23];
    const float* ob2     = (const float*)d_in[24];
    float* out = (float*)d_out;

    float *x0, *y, *x, *Qb, *Kb, *Vb, *Ab, *Ob, *T1, *Hf, *Cc, *M1, *M2, *Sb;
    cudaGetSymbolAddress((void**)&x0, g_x0);
    cudaGetSymbolAddress((void**)&y,  g_y);
    cudaGetSymbolAddress((void**)&x,  g_x);
    cudaGetSymbolAddress((void**)&Qb, g_Q);
    cudaGetSymbolAddress((void**)&Kb, g_K);
    cudaGetSymbolAddress((void**)&Vb, g_V);
    cudaGetSymbolAddress((void**)&Ab, g_A);
    cudaGetSymbolAddress((void**)&Ob, g_O);
    cudaGetSymbolAddress((void**)&T1, g_T1);
    cudaGetSymbolAddress((void**)&Hf, g_Hf);
    cudaGetSymbolAddress((void**)&Cc, g_Cc);
    cudaGetSymbolAddress((void**)&M1, g_M1);
    cudaGetSymbolAddress((void**)&M2, g_M2);
    cudaGetSymbolAddress((void**)&Sb, g_S);

    embed_kernel<<<MTOK, 128>>>(c_data, ca_data, c_emb, ca_emb, x0, y, x);

    for (int li = 0; li < 6; li++) {
        int strict, ap;
        float* qio; const float *kin, *vin;
        if (li < 2)            { strict = 0; ap = 1; qio = y; kin = x0; vin = y; }
        else {
            int j = li - 2;
            if ((j & 1) == 0)  { strict = 0; ap = 0; qio = x; kin = x;  vin = x; }
            else               { strict = 1; ap = 1; qio = x; kin = x;  vin = y; }
        }
        const float* Wk_i = Wk + (size_t)li * Dm * Dm;  const float* bk_i = bk + li * Dm;
        const float* Wv_i = Wv + (size_t)li * Dm * Dm;  const float* bv_i = bv + li * Dm;
        const float* Wo_i = Wo + (size_t)li * Dm * Dm;  const float* bo_i = bo + li * Dm;

        gemm(qio, Wk_i, bk_i, Qb, MTOK, Dm, Dm, 0);
        const float* Kuse;
        if (kin == qio) Kuse = Qb;
        else { gemm(kin, Wk_i, bk_i, Kb, MTOK, Dm, Dm, 0); Kuse = Kb; }
        gemm(vin, Wv_i, bv_i, Vb, MTOK, Dm, Dm, 0);

        score_kernel<<<dim3(8, 8, NBH), 256>>>(Qb, Kuse, Sb);
        decay_softmax_kernel<<<dim3(Sq, NBH), 256>>>(Sb, gammas, li, strict);
        av_kernel<<<dim3(8, NBH), 256>>>(Sb, Vb, Ab);

        gemm(Ab, Wo_i, bo_i, Ob, MTOK, Dm, Dm, 0);
        ln_add_kernel<<<MTOK, 128>>>(qio, Ob, ln1s + li*Dm, ln1b + li*Dm, ap ? T1 : qio);
        if (ap) {
            gemm(T1, W1 + (size_t)li * Dm * FF, b1 + li * FF, Hf, MTOK, FF, Dm, 1);
            gemm(Hf, W2 + (size_t)li * FF * Dm, b2 + li * Dm, Ob, MTOK, Dm, FF, 0);
            ln_add_kernel<<<MTOK, 128>>>(T1, Ob, ln2s + li*Dm, ln2b + li*Dm, qio);
        }
    }

    concat_kernel<<<MTOK, 256>>>(x, x0, Cc);
    gemm(Cc, oW0, ob0, M1, MTOK, 512,  2 * Dm, 1);
    gemm(M1, oW1, ob1, M2, MTOK, 1024, 512,    1);
    gemm(M2, oW2, ob2, out, MTOK, NCPT, 1024,  0);
}

// round 5
// speedup vs baseline: 1.6840x; 1.5217x over previous
#include <cuda_runtime.h>
#include <cuda_bf16.h>
#include <math.h>
#include <stdint.h>

#define Bsz 8
#define Sq  512
#define Dm  512
#define Hh  8
#define DK  64
#define FF  2048
#define MTOK (Bsz*Sq)   // 4096
#define NCPT 1000
#define NBH (Bsz*Hh)    // 64

// ---------------- scratch (device globals; no allocation) ----------------
__device__ float g_x0[MTOK*Dm];
__device__ float g_y [MTOK*Dm];
__device__ float g_x [MTOK*Dm];
__device__ float g_Q [MTOK*Dm];
__device__ float g_K [MTOK*Dm];
__device__ float g_V [MTOK*Dm];
__device__ float g_A [MTOK*Dm];
__device__ float g_O [MTOK*Dm];
__device__ float g_T1[MTOK*Dm];
__device__ float g_Hf[MTOK*FF];
__device__ float g_Cc[MTOK*2*Dm];
__device__ float g_M1[MTOK*512];
__device__ float g_M2[MTOK*1024];
__device__ float g_S [NBH*Sq*Sq];   // 64 MB score/attn-weight scratch

// ---------------- embed ----------------
__global__ void embed_kernel(const int* __restrict__ c_data, const int* __restrict__ ca_data,
                             const float* __restrict__ c_emb, const float* __restrict__ ca_emb,
                             float* __restrict__ x0, float* __restrict__ y, float* __restrict__ x)
{
    int r = blockIdx.x;
    int c = c_data[r];
    int resp = (ca_data[r] - c) / NCPT;
    const float* er = c_emb + (size_t)c * Dm;
    const float* ar = ca_emb + (size_t)resp * Dm;
    for (int j = threadIdx.x; j < Dm; j += blockDim.x) {
        float v = er[j];
        x0[(size_t)r*Dm + j] = v;
        x [(size_t)r*Dm + j] = v;
        y [(size_t)r*Dm + j] = v + ar[j];
    }
}

// ---------------- bf16x3 tensor-core GEMM -----------------------------------
__device__ __forceinline__ void mma_bf16(float* c, const uint32_t* a, const uint32_t* b) {
    asm volatile(
        "mma.sync.aligned.m16n8k16.row.col.f32.bf16.bf16.f32 "
        "{%0,%1,%2,%3}, {%4,%5,%6,%7}, {%8,%9}, {%0,%1,%2,%3};"
        : "+f"(c[0]), "+f"(c[1]), "+f"(c[2]), "+f"(c[3])
        : "r"(a[0]), "r"(a[1]), "r"(a[2]), "r"(a[3]), "r"(b[0]), "r"(b[1]));
}

#define GP 138   // uint2 pitch: loads conflict-free, stores ~1/8 2-way

__global__ __launch_bounds__(512)
void gemm_bf3(const float* __restrict__ A, const float* __restrict__ W,
              const float* __restrict__ bias, float* __restrict__ C,
              int M, int N, int K, int relu)
{
    __shared__ uint2 As[2][8][GP];
    __shared__ uint2 Bs[2][8][GP];

    int tid = threadIdx.x;
    int row0 = blockIdx.y * 128, col0 = blockIdx.x * 128;
    int warp = tid >> 5, lane = tid & 31;
    int wm = warp & 3, wn = warp >> 2;      // 4x4 warps, 32x32 tiles
    int g = lane >> 2, tig = lane & 3;

    bool isA = tid < 256;
    int arow = (tid & 255) >> 1;            // A threads: row 0..127
    int aks = tid & 1;                      // k-half
    int bn = tid & 127;                     // B threads: col 0..127
    int bks = (tid >> 7) & 1;
    const float* Ap = A + (size_t)(row0 + arow) * K + aks * 8;
    int bcg = col0 + bn;
    bool bok = bcg < N;

    float acc[2][4][4];
#pragma unroll
    for (int i = 0; i < 2; i++)
#pragma unroll
        for (int j = 0; j < 4; j++)
#pragma unroll
            for (int q = 0; q < 4; q++) acc[i][j][q] = 0.f;

    float rv[8];
    int T = K >> 4;

    auto ldg = [&](int t) {
        if (isA) {
            const float* p = Ap + t * 16;
            float4 a0 = *(const float4*)p;
            float4 a1 = *(const float4*)(p + 4);
            rv[0]=a0.x; rv[1]=a0.y; rv[2]=a0.z; rv[3]=a0.w;
            rv[4]=a1.x; rv[5]=a1.y; rv[6]=a1.z; rv[7]=a1.w;
        } else {
            const float* p = W + (size_t)(t * 16 + bks * 8) * N + bcg;
#pragma unroll
            for (int j = 0; j < 8; j++) rv[j] = bok ? p[(size_t)j * N] : 0.f;
        }
    };
    auto sts = [&](int bf) {
        int ks = isA ? aks : bks;
        int r  = isA ? arow : bn;
        uint2 (*dst)[GP] = isA ? As[bf] : Bs[bf];
#pragma unroll
        for (int jj = 0; jj < 4; jj++) {
            float x0 = rv[2*jj], x1 = rv[2*jj+1];
            __nv_bfloat16 h0 = __float2bfloat16(x0);
            __nv_bfloat16 h1 = __float2bfloat16(x1);
            float r0 = x0 - __bfloat162float(h0);
            float r1 = x1 - __bfloat162float(h1);
            __nv_bfloat162 hh; hh.x = h0; hh.y = h1;
            __nv_bfloat162 ll = __floats2bfloat162_rn(r0, r1);
            dst[jj*2 + ks][r] = make_uint2(*(uint32_t*)&hh, *(uint32_t*)&ll);
        }
    };

    ldg(0); sts(0);
    __syncthreads();

    int buf = 0;
    for (int t = 0; t < T; t++) {
        if (t + 1 < T) ldg(t + 1);
        uint32_t ah[2][4], al[2][4];
#pragma unroll
        for (int mt = 0; mt < 2; mt++) {
            int r = wm * 32 + mt * 16 + g;
            uint2 ua = As[buf][2*tig    ][r];
            uint2 ub = As[buf][2*tig    ][r + 8];
            uint2 uc = As[buf][2*tig + 1][r];
            uint2 ud = As[buf][2*tig + 1][r + 8];
            ah[mt][0]=ua.x; ah[mt][1]=ub.x; ah[mt][2]=uc.x; ah[mt][3]=ud.x;
            al[mt][0]=ua.y; al[mt][1]=ub.y; al[mt][2]=uc.y; al[mt][3]=ud.y;
        }
#pragma unroll
        for (int nt = 0; nt < 4; nt++) {
            int n0 = wn * 32 + nt * 8 + g;
            uint2 u0 = Bs[buf][2*tig    ][n0];
            uint2 u1 = Bs[buf][2*tig + 1][n0];
            uint32_t bh[2] = {u0.x, u1.x};
            uint32_t bl[2] = {u0.y, u1.y};
#pragma unroll
            for (int mt = 0; mt < 2; mt++) {
                mma_bf16(acc[mt][nt], ah[mt], bh);
                mma_bf16(acc[mt][nt], al[mt], bh);
                mma_bf16(acc[mt][nt], ah[mt], bl);
            }
        }
        if (t + 1 < T) {
            sts(buf ^ 1);
            __syncthreads();
            buf ^= 1;
        }
    }

    // epilogue: thread (g,tig): rows +g,+g+8; cols +2tig,+2tig+1
#pragma unroll
    for (int mt = 0; mt < 2; mt++) {
        int rbase = row0 + wm * 32 + mt * 16;
#pragma unroll
        for (int nt = 0; nt < 4; nt++) {
            int cb = col0 + wn * 32 + nt * 8 + 2 * tig;
            float b0 = (cb < N) ? bias[cb] : 0.f;
            float b1 = (cb + 1 < N) ? bias[cb + 1] : 0.f;
#pragma unroll
            for (int half = 0; half < 2; half++) {
                int r = rbase + g + half * 8;
                float v0 = acc[mt][nt][half * 2 + 0] + b0;
                float v1 = acc[mt][nt][half * 2 + 1] + b1;
                if (relu) { v0 = fmaxf(v0, 0.f); v1 = fmaxf(v1, 0.f); }
                if (cb < N)     C[(size_t)r * N + cb]     = v0;
                if (cb + 1 < N) C[(size_t)r * N + cb + 1] = v1;
            }
        }
    }
}

// ---------------- attention part 1: scores (lower-tri tiles) ----------------
__global__ __launch_bounds__(256)
void score_kernel(const float* __restrict__ Q, const float* __restrict__ Kp,
                  float* __restrict__ S)
{
    int bx = blockIdx.x, by = blockIdx.y;
    if (bx > by) return;                 // fully masked tile
    int z = blockIdx.z;
    int b = z >> 3, h = z & 7;
    __shared__ float Qs[64][68];         // [d][q]
    __shared__ float Ks[64][68];         // [d][k]
    int tid = threadIdx.x;
    const float* Qbase = Q  + ((size_t)(b * Sq + by * 64)) * Dm + h * DK;
    const float* Kbase = Kp + ((size_t)(b * Sq + bx * 64)) * Dm + h * DK;
#pragma unroll
    for (int l = 0; l < 4; l++) {
        int idx = tid + l * 256;
        int r = idx >> 4, c4 = (idx & 15) * 4;
        float4 q4 = *(const float4*)(Qbase + (size_t)r * Dm + c4);
        Qs[c4 + 0][r] = q4.x; Qs[c4 + 1][r] = q4.y;
        Qs[c4 + 2][r] = q4.z; Qs[c4 + 3][r] = q4.w;
        float4 k4 = *(const float4*)(Kbase + (size_t)r * Dm + c4);
        Ks[c4 + 0][r] = k4.x; Ks[c4 + 1][r] = k4.y;
        Ks[c4 + 2][r] = k4.z; Ks[c4 + 3][r] = k4.w;
    }
    __syncthreads();
    int tx = tid & 15, ty = tid >> 4;
    float acc[4][4];
#pragma unroll
    for (int i = 0; i < 4; i++)
#pragma unroll
        for (int j = 0; j < 4; j++) acc[i][j] = 0.f;
#pragma unroll 8
    for (int d = 0; d < 64; d++) {
        float4 a4 = *(const float4*)&Qs[d][ty * 4];
        float4 b4 = *(const float4*)&Ks[d][tx * 4];
        float a[4] = {a4.x, a4.y, a4.z, a4.w};
        float b[4] = {b4.x, b4.y, b4.z, b4.w};
#pragma unroll
        for (int i = 0; i < 4; i++)
#pragma unroll
            for (int j = 0; j < 4; j++) acc[i][j] = fmaf(a[i], b[j], acc[i][j]);
    }
    float* Srow = S + ((size_t)z * Sq + by * 64) * Sq + bx * 64;
#pragma unroll
    for (int i = 0; i < 4; i++)
#pragma unroll
        for (int j = 0; j < 4; j++)
            Srow[(size_t)(ty * 4 + i) * Sq + tx * 4 + j] = acc[i][j] * 0.125f;
}

// ---------------- attention part 2: register-resident softmax/decay ---------
__global__ __launch_bounds__(256)
void decay_softmax_kernel(float* __restrict__ S, const float* __restrict__ gammas,
                          int layer, int strict)
{
    __shared__ float shw[8];
    __shared__ float shpre[8];
    __shared__ float shb;
    int i = blockIdx.x, z = blockIdx.y, h = z & 7;
    int tid = threadIdx.x, lane = tid & 31, wid = tid >> 5;
    float* row = S + ((size_t)z * Sq + i) * Sq;
    int kmax = i - strict;
    int k0 = 2 * tid, k1 = 2 * tid + 1;
    if (kmax < 0) {
        *(float2*)&row[k0] = make_float2(0.f, 0.f);
        return;
    }
    float2 rw = *(const float2*)&row[k0];
    float s0 = rw.x, s1 = rw.y;
    bool v0 = (k0 <= kmax), v1 = (k1 <= kmax);

    // --- max #1 ---
    float lm = fmaxf(v0 ? s0 : -3e38f, v1 ? s1 : -3e38f);
#pragma unroll
    for (int o = 16; o; o >>= 1) lm = fmaxf(lm, __shfl_xor_sync(~0u, lm, o));
    if (lane == 0) shw[wid] = lm;
    __syncthreads();
    if (tid == 0) {
        float m = shw[0];
#pragma unroll
        for (int w = 1; w < 8; w++) m = fmaxf(m, shw[w]);
        shb = m;
    }
    __syncthreads();
    float m1 = shb;

    float p0 = v0 ? expf(s0 - m1) : 0.f;
    float p1 = v1 ? expf(s1 - m1) : 0.f;

    // --- sum #1 ---
    float ls = p0 + p1;
#pragma unroll
    for (int o = 16; o; o >>= 1) ls += __shfl_xor_sync(~0u, ls, o);
    if (lane == 0) shw[wid] = ls;
    __syncthreads();
    if (tid == 0) {
        float m = 0.f;
#pragma unroll
        for (int w = 0; w < 8; w++) m += shw[w];
        shb = m;
    }
    __syncthreads();
    float inv1 = 1.f / shb;
    p0 *= inv1; p1 *= inv1;

    // --- inclusive cumsum (shuffle scan) ---
    float s = p0 + p1;
#pragma unroll
    for (int o = 1; o < 32; o <<= 1) {
        float t = __shfl_up_sync(~0u, s, o);
        if (lane >= o) s += t;
    }
    if (lane == 31) shw[wid] = s;
    __syncthreads();
    if (wid == 0 && lane < 8) {
        float t = shw[lane];
#pragma unroll
        for (int o = 1; o < 8; o <<= 1) {
            float tt = __shfl_up_sync(0xffu, t, o);
            if (lane >= o) t += tt;
        }
        shpre[lane] = t;
    }
    __syncthreads();
    float base = wid ? shpre[wid - 1] : 0.f;
    float cum1 = base + s;
    float cum0 = cum1 - p1;
    float total = shpre[7];

    float gm = gammas[layer * Hh + h];
    float sp = (gm > 20.f) ? gm : log1pf(expf(gm));
    float gamma = -sp;

    float suf0 = total - cum0, suf1 = total - cum1;
    float d0 = sqrtf(fmaxf(suf0 * (float)(i - k0), 0.f));
    float d1 = sqrtf(fmaxf(suf1 * (float)(i - k1), 0.f));
    float te0 = fminf(fmaxf(expf(d0 * gamma), 1e-5f), 1e5f);
    float te1 = fminf(fmaxf(expf(d1 * gamma), 1e-5f), 1e5f);
    float t0 = s0 * te0, t1 = s1 * te1;

    // --- max #2 ---
    lm = fmaxf(v0 ? t0 : -3e38f, v1 ? t1 : -3e38f);
#pragma unroll
    for (int o = 16; o; o >>= 1) lm = fmaxf(lm, __shfl_xor_sync(~0u, lm, o));
    if (lane == 0) shw[wid] = lm;
    __syncthreads();
    if (tid == 0) {
        float m = shw[0];
#pragma unroll
        for (int w = 1; w < 8; w++) m = fmaxf(m, shw[w]);
        shb = m;
    }
    __syncthreads();
    float m2 = shb;

    float q0 = v0 ? expf(t0 - m2) : 0.f;
    float q1 = v1 ? expf(t1 - m2) : 0.f;

    // --- sum #2 ---
    ls = q0 + q1;
#pragma unroll
    for (int o = 16; o; o >>= 1) ls += __shfl_xor_sync(~0u, ls, o);
    if (lane == 0) shw[wid] = ls;
    __syncthreads();
    if (tid == 0) {
        float m = 0.f;
#pragma unroll
        for (int w = 0; w < 8; w++) m += shw[w];
        shb = m;
    }
    __syncthreads();
    float inv2 = 1.f / shb;

    *(float2*)&row[k0] = make_float2(q0 * inv2, q1 * inv2);
}

// ---------------- attention part 3: O = P @ V ----------------
__global__ __launch_bounds__(256)
void av_kernel(const float* __restrict__ S, const float* __restrict__ V,
               float* __restrict__ O)
{
    int qt = blockIdx.x, z = blockIdx.y;
    int b = z >> 3, h = z & 7;
    __shared__ float Ps[16][68];   // [k][q]
    __shared__ float Vs[16][68];   // [k][d]
    int tid = threadIdx.x, tx = tid & 15, ty = tid >> 4;
    float acc[4][4];
#pragma unroll
    for (int i = 0; i < 4; i++)
#pragma unroll
        for (int j = 0; j < 4; j++) acc[i][j] = 0.f;

    const float* Srow  = S + ((size_t)z * Sq + qt * 64) * Sq;
    const float* Vbase = V + ((size_t)b * Sq) * Dm + h * DK;
    int nkt = qt * 4 + 4;            // P[q][k]=0 for k>q -> skip upper tiles
    for (int kt = 0; kt < nkt; kt++) {
        int k0 = kt * 16;
        {
            int q = tid >> 2, kc = (tid & 3) * 4;
            float4 p4 = *(const float4*)(Srow + (size_t)q * Sq + k0 + kc);
            Ps[kc + 0][q] = p4.x; Ps[kc + 1][q] = p4.y;
            Ps[kc + 2][q] = p4.z; Ps[kc + 3][q] = p4.w;
            int kr = tid >> 4, d4 = (tid & 15) * 4;
            *(float4*)&Vs[kr][d4] = *(const float4*)(Vbase + (size_t)(k0 + kr) * Dm + d4);
        }
        __syncthreads();
#pragma unroll
        for (int kk = 0; kk < 16; kk++) {
            float4 a4 = *(const float4*)&Ps[kk][ty * 4];
            float4 b4 = *(const float4*)&Vs[kk][tx * 4];
            float a[4] = {a4.x, a4.y, a4.z, a4.w};
            float b[4] = {b4.x, b4.y, b4.z, b4.w};
#pragma unroll
            for (int i = 0; i < 4; i++)
#pragma unroll
                for (int j = 0; j < 4; j++) acc[i][j] = fmaf(a[i], b[j], acc[i][j]);
        }
        __syncthreads();
    }
    float* Orow = O + ((size_t)(b * Sq + qt * 64)) * Dm + h * DK;
#pragma unroll
    for (int i = 0; i < 4; i++)
#pragma unroll
        for (int j = 0; j < 4; j++)
            Orow[(size_t)(ty * 4 + i) * Dm + tx * 4 + j] = acc[i][j];
}

// ---------------- residual + LayerNorm: out = LN(A + B) ----------------
__global__ void ln_add_kernel(const float* __restrict__ A, const float* __restrict__ Bv,
                              const float* __restrict__ sc, const float* __restrict__ bi,
                              float* __restrict__ out)
{
    int r = blockIdx.x, tid = threadIdx.x;
    const float* a  = A  + (size_t)r * Dm;
    const float* bq = Bv + (size_t)r * Dm;
    float v[4];
    float s = 0.f, s2 = 0.f;
#pragma unroll
    for (int j = 0; j < 4; j++) {
        int c = tid + j * 128;
        float t = a[c] + bq[c];
        v[j] = t; s += t; s2 += t * t;
    }
    __shared__ float rs[4], rs2[4];
#pragma unroll
    for (int o = 16; o > 0; o >>= 1) {
        s  += __shfl_down_sync(0xffffffffu, s,  o);
        s2 += __shfl_down_sync(0xffffffffu, s2, o);
    }
    int w = tid >> 5, l = tid & 31;
    if (l == 0) { rs[w] = s; rs2[w] = s2; }
    __syncthreads();
    float ss  = rs[0] + rs[1] + rs[2] + rs[3];
    float ss2 = rs2[0] + rs2[1] + rs2[2] + rs2[3];
    float mean = ss / 512.f;
    float var  = ss2 / 512.f - mean * mean;
    float rstd = rsqrtf(var + 1e-5f);
#pragma unroll
    for (int j = 0; j < 4; j++) {
        int c = tid + j * 128;
        out[(size_t)r * Dm + c] = (v[j] - mean) * rstd * sc[c] + bi[c];
    }
}

// ---------------- concat [x, x0] ----------------
__global__ void concat_kernel(const float* __restrict__ x, const float* __restrict__ x0,
                              float* __restrict__ out)
{
    int r = blockIdx.x;
    for (int j = threadIdx.x; j < 2 * Dm; j += blockDim.x)
        out[(size_t)r * 2 * Dm + j] = (j < Dm) ? x[(size_t)r*Dm + j]
                                               : x0[(size_t)r*Dm + j - Dm];
}

// ---------------- host ----------------
static inline void gemm(const float* A, const float* W, const float* bias,
                        float* C, int M, int N, int K, int relu)
{
    dim3 grid((N + 127) / 128, M / 128);
    gemm_bf3<<<grid, 512>>>(A, W, bias, C, M, N, K, relu);
}

extern "C" void kernel_launch(void* const* d_in, const int* in_sizes, int n_in,
                              void* d_out, int out_size)
{
    const int*   c_data  = (const int*)  d_in[0];
    const int*   ca_data = (const int*)  d_in[1];
    const float* c_emb   = (const float*)d_in[2];
    const float* ca_emb  = (const float*)d_in[3];
    const float* Wk      = (const float*)d_in[4];
    const float* bk      = (const float*)d_in[5];
    const float* Wv      = (const float*)d_in[6];
    const float* bv      = (const float*)d_in[7];
    const float* Wo      = (const float*)d_in[8];
    const float* bo      = (const float*)d_in[9];
    const float* gammas  = (const float*)d_in[10];
    const float* ln1s    = (const float*)d_in[11];
    const float* ln1b    = (const float*)d_in[12];
    const float* W1      = (const float*)d_in[13];
    const float* b1      = (const float*)d_in[14];
    const float* W2      = (const float*)d_in[15];
    const float* b2      = (const float*)d_in[16];
    const float* ln2s    = (const float*)d_in[17];
    const float* ln2b    = (const float*)d_in[18];
    const float* oW0     = (const float*)d_in[19];
    const float* ob0     = (const float*)d_in[20];
    const float* oW1     = (const float*)d_in[21];
    const float* ob1     = (const float*)d_in[22];
    const float* oW2     = (const float*)d_in[23];
    const float* ob2     = (const float*)d_in[24];
    float* out = (float*)d_out;

    float *x0, *y, *x, *Qb, *Kb, *Vb, *Ab, *Ob, *T1, *Hf, *Cc, *M1, *M2, *Sb;
    cudaGetSymbolAddress((void**)&x0, g_x0);
    cudaGetSymbolAddress((void**)&y,  g_y);
    cudaGetSymbolAddress((void**)&x,  g_x);
    cudaGetSymbolAddress((void**)&Qb, g_Q);
    cudaGetSymbolAddress((void**)&Kb, g_K);
    cudaGetSymbolAddress((void**)&Vb, g_V);
    cudaGetSymbolAddress((void**)&Ab, g_A);
    cudaGetSymbolAddress((void**)&Ob, g_O);
    cudaGetSymbolAddress((void**)&T1, g_T1);
    cudaGetSymbolAddress((void**)&Hf, g_Hf);
    cudaGetSymbolAddress((void**)&Cc, g_Cc);
    cudaGetSymbolAddress((void**)&M1, g_M1);
    cudaGetSymbolAddress((void**)&M2, g_M2);
    cudaGetSymbolAddress((void**)&Sb, g_S);

    embed_kernel<<<MTOK, 128>>>(c_data, ca_data, c_emb, ca_emb, x0, y, x);

    for (int li = 0; li < 6; li++) {
        int strict, ap;
        float* qio; const float *kin, *vin;
        if (li < 2)            { strict = 0; ap = 1; qio = y; kin = x0; vin = y; }
        else {
            int j = li - 2;
            if ((j & 1) == 0)  { strict = 0; ap = 0; qio = x; kin = x;  vin = x; }
            else               { strict = 1; ap = 1; qio = x; kin = x;  vin = y; }
        }
        const float* Wk_i = Wk + (size_t)li * Dm * Dm;  const float* bk_i = bk + li * Dm;
        const float* Wv_i = Wv + (size_t)li * Dm * Dm;  const float* bv_i = bv + li * Dm;
        const float* Wo_i = Wo + (size_t)li * Dm * Dm;  const float* bo_i = bo + li * Dm;

        gemm(qio, Wk_i, bk_i, Qb, MTOK, Dm, Dm, 0);
        const float* Kuse;
        if (kin == qio) Kuse = Qb;
        else { gemm(kin, Wk_i, bk_i, Kb, MTOK, Dm, Dm, 0); Kuse = Kb; }
        gemm(vin, Wv_i, bv_i, Vb, MTOK, Dm, Dm, 0);

        score_kernel<<<dim3(8, 8, NBH), 256>>>(Qb, Kuse, Sb);
        decay_softmax_kernel<<<dim3(Sq, NBH), 256>>>(Sb, gammas, li, strict);
        av_kernel<<<dim3(8, NBH), 256>>>(Sb, Vb, Ab);

        gemm(Ab, Wo_i, bo_i, Ob, MTOK, Dm, Dm, 0);
        ln_add_kernel<<<MTOK, 128>>>(qio, Ob, ln1s + li*Dm, ln1b + li*Dm, ap ? T1 : qio);
        if (ap) {
            gemm(T1, W1 + (size_t)li * Dm * FF, b1 + li * FF, Hf, MTOK, FF, Dm, 1);
            gemm(Hf, W2 + (size_t)li * FF * Dm, b2 + li * Dm, Ob, MTOK, Dm, FF, 0);
            ln_add_kernel<<<MTOK, 128>>>(T1, Ob, ln2s + li*Dm, ln2b + li*Dm, qio);
        }
    }

    concat_kernel<<<MTOK, 256>>>(x, x0, Cc);
    gemm(Cc, oW0, ob0, M1, MTOK, 512,  2 * Dm, 1);
    gemm(M1, oW1, ob1, M2, MTOK, 1024, 512,    1);
    gemm(M2, oW2, ob2, out, MTOK, NCPT, 1024,  0);
}

// round 6
// speedup vs baseline: 1.7480x; 1.0380x over previous
#include <cuda_runtime.h>
#include <cuda_bf16.h>
#include <math.h>
#include <stdint.h>

#define Bsz 8
#define Sq  512
#define Dm  512
#define Hh  8
#define DK  64
#define FF  2048
#define MTOK (Bsz*Sq)   // 4096
#define NCPT 1000
#define NBH (Bsz*Hh)    // 64

// ---------------- scratch (device globals; no allocation) ----------------
// fp32 buffers
__device__ float g_x0[MTOK*Dm];
__device__ float g_y [MTOK*Dm];
__device__ float g_x [MTOK*Dm];
__device__ float g_QV[MTOK*1024];
__device__ float g_K [MTOK*Dm];
__device__ float g_Ob[MTOK*Dm];
__device__ float g_T1[MTOK*Dm];
__device__ float g_S [NBH*Sq*Sq];          // 64 MB scores
// split (hi/lo bf16 pair-packed) activation buffers: uint2 per k-pair
__device__ uint2 g_x0s[MTOK*256];
__device__ uint2 g_ys [MTOK*256];
__device__ uint2 g_xs [MTOK*256];
__device__ uint2 g_T1s[MTOK*256];
__device__ uint2 g_Abs[MTOK*256];
__device__ uint2 g_Hfs[MTOK*1024];
__device__ uint2 g_Ccs[MTOK*512];
__device__ uint2 g_M1s[MTOK*256];
__device__ uint2 g_M2s[MTOK*512];
// split weights
__device__ uint2 g_Wqvs[6*256*1024];
__device__ uint2 g_Wos [6*256*512];
__device__ uint2 g_W1s [6*256*2048];
__device__ uint2 g_W2s [6*1024*512];
__device__ uint2 g_oW0s[512*512];
__device__ uint2 g_oW1s[256*1024];
__device__ uint2 g_oW2s[512*1000];
__device__ float g_bqv[6*1024];

// ---------------- split helper ----------------
__device__ __forceinline__ uint2 split2(float v0, float v1) {
    __nv_bfloat16 h0 = __float2bfloat16(v0);
    __nv_bfloat16 h1 = __float2bfloat16(v1);
    float r0 = v0 - __bfloat162float(h0);
    float r1 = v1 - __bfloat162float(h1);
    __nv_bfloat162 hh; hh.x = h0; hh.y = h1;
    __nv_bfloat162 ll = __floats2bfloat162_rn(r0, r1);
    return make_uint2(*(uint32_t*)&hh, *(uint32_t*)&ll);
}

// ---------------- weight split: W[K][N] fp32 -> out[K/2][ldo] uint2 ----------
__global__ void split_w(const float* __restrict__ W, uint2* __restrict__ out,
                        int K, int N, int ldo, int colOff,
                        size_t inStride, size_t outStride)
{
    int z = blockIdx.z;
    const float* Wz = W + (size_t)z * inStride;
    uint2* oz = out + (size_t)z * outStride + colOff;
    int KP = K >> 1;
    int total = KP * N;
    for (int idx = blockIdx.x * blockDim.x + threadIdx.x; idx < total;
         idx += gridDim.x * blockDim.x) {
        int kp = idx / N, n = idx - kp * N;
        float v0 = Wz[(size_t)(2 * kp) * N + n];
        float v1 = Wz[(size_t)(2 * kp + 1) * N + n];
        oz[(size_t)kp * ldo + n] = split2(v0, v1);
    }
}

__global__ void pack_bqv(const float* __restrict__ bk, const float* __restrict__ bv,
                         float* __restrict__ bqv)
{
    int i = blockIdx.x * blockDim.x + threadIdx.x;
    if (i >= 6 * 1024) return;
    int li = i >> 10, j = i & 1023;
    bqv[i] = (j < 512) ? bk[li * 512 + j] : bv[li * 512 + j - 512];
}

// ---------------- embed (writes fp32 + splits) ----------------
__global__ void embed_kernel(const int* __restrict__ c_data, const int* __restrict__ ca_data,
                             const float* __restrict__ c_emb, const float* __restrict__ ca_emb,
                             float* __restrict__ x0, float* __restrict__ y, float* __restrict__ x,
                             uint2* __restrict__ x0s, uint2* __restrict__ ys, uint2* __restrict__ xs)
{
    int r = blockIdx.x;
    int c = c_data[r];
    int resp = (ca_data[r] - c) / NCPT;
    const float* er = c_emb + (size_t)c * Dm;
    const float* ar = ca_emb + (size_t)resp * Dm;
    int j = threadIdx.x * 4;               // 128 threads x 4 cols
    float4 e4 = *(const float4*)(er + j);
    float4 a4 = *(const float4*)(ar + j);
    float y0 = e4.x + a4.x, y1 = e4.y + a4.y, y2 = e4.z + a4.z, y3 = e4.w + a4.w;
    *(float4*)&x0[(size_t)r*Dm + j] = e4;
    *(float4*)&x [(size_t)r*Dm + j] = e4;
    *(float4*)&y [(size_t)r*Dm + j] = make_float4(y0, y1, y2, y3);
    size_t sb = (size_t)r * 256 + (j >> 1);
    uint2 s0 = split2(e4.x, e4.y), s1 = split2(e4.z, e4.w);
    x0s[sb] = s0; x0s[sb + 1] = s1;
    xs [sb] = s0; xs [sb + 1] = s1;
    ys [sb] = split2(y0, y1); ys[sb + 1] = split2(y2, y3);
}

// ---------------- bf16x3 tensor-core GEMM, pre-split operands ---------------
__device__ __forceinline__ void mma_bf16(float* c, const uint32_t* a, const uint32_t* b) {
    asm volatile(
        "mma.sync.aligned.m16n8k16.row.col.f32.bf16.bf16.f32 "
        "{%0,%1,%2,%3}, {%4,%5,%6,%7}, {%8,%9}, {%0,%1,%2,%3};"
        : "+f"(c[0]), "+f"(c[1]), "+f"(c[2]), "+f"(c[3])
        : "r"(a[0]), "r"(a[1]), "r"(a[2]), "r"(a[3]), "r"(b[0]), "r"(b[1]));
}

#define GP 138

__global__ __launch_bounds__(512)
void gemm_hl(const uint2* __restrict__ Ahl, const uint2* __restrict__ Whl, int ldw,
             const float* __restrict__ bias, float* __restrict__ C, int ldc,
             uint2* __restrict__ Chl,
             int M, int N, int K, int relu)
{
    __shared__ uint2 As[2][8][GP];
    __shared__ uint2 Bs[2][8][GP];

    int tid = threadIdx.x;
    int row0 = blockIdx.y * 128, col0 = blockIdx.x * 128;
    int warp = tid >> 5, lane = tid & 31;
    int wm = warp & 3, wn = warp >> 2;      // 4x4 warps, 32x32 tiles
    int g = lane >> 2, tig = lane & 3;

    bool isA = tid < 256;
    int arow = (tid & 255) >> 1;
    int aks = tid & 1;
    int bn = tid & 127;
    int bks = (tid >> 7) & 1;
    int KP = K >> 1;
    const uint2* Ap = Ahl + (size_t)(row0 + arow) * KP + aks * 4;
    int bcg = col0 + bn;
    bool bok = bcg < N;

    float acc[2][4][4];
#pragma unroll
    for (int i = 0; i < 2; i++)
#pragma unroll
        for (int j = 0; j < 4; j++)
#pragma unroll
            for (int q = 0; q < 4; q++) acc[i][j][q] = 0.f;

    uint2 rv[4];
    int T = K >> 4;

    auto ldg = [&](int t) {
        if (isA) {
            const uint2* p = Ap + t * 8;
            uint4 u0 = *(const uint4*)p;
            uint4 u1 = *(const uint4*)(p + 2);
            rv[0] = make_uint2(u0.x, u0.y); rv[1] = make_uint2(u0.z, u0.w);
            rv[2] = make_uint2(u1.x, u1.y); rv[3] = make_uint2(u1.z, u1.w);
        } else {
            const uint2* p = Whl + (size_t)(t * 8 + bks * 4) * ldw + bcg;
#pragma unroll
            for (int j = 0; j < 4; j++) rv[j] = bok ? p[(size_t)j * ldw] : make_uint2(0, 0);
        }
    };
    auto sts = [&](int bf) {
        int ks = isA ? aks : bks;
        int r  = isA ? arow : bn;
        uint2 (*dst)[GP] = isA ? As[bf] : Bs[bf];
#pragma unroll
        for (int jj = 0; jj < 4; jj++) dst[jj * 2 + ks][r] = rv[jj];
    };

    ldg(0); sts(0);
    __syncthreads();

    int buf = 0;
    for (int t = 0; t < T; t++) {
        if (t + 1 < T) ldg(t + 1);
        uint32_t ah[2][4], al[2][4];
#pragma unroll
        for (int mt = 0; mt < 2; mt++) {
            int r = wm * 32 + mt * 16 + g;
            uint2 ua = As[buf][2*tig    ][r];
            uint2 ub = As[buf][2*tig    ][r + 8];
            uint2 uc = As[buf][2*tig + 1][r];
            uint2 ud = As[buf][2*tig + 1][r + 8];
            ah[mt][0]=ua.x; ah[mt][1]=ub.x; ah[mt][2]=uc.x; ah[mt][3]=ud.x;
            al[mt][0]=ua.y; al[mt][1]=ub.y; al[mt][2]=uc.y; al[mt][3]=ud.y;
        }
#pragma unroll
        for (int nt = 0; nt < 4; nt++) {
            int n0 = wn * 32 + nt * 8 + g;
            uint2 u0 = Bs[buf][2*tig    ][n0];
            uint2 u1 = Bs[buf][2*tig + 1][n0];
            uint32_t bh[2] = {u0.x, u1.x};
            uint32_t bl[2] = {u0.y, u1.y};
#pragma unroll
            for (int mt = 0; mt < 2; mt++) {
                mma_bf16(acc[mt][nt], ah[mt], bh);
                mma_bf16(acc[mt][nt], al[mt], bh);
                mma_bf16(acc[mt][nt], ah[mt], bl);
            }
        }
        if (t + 1 < T) {
            sts(buf ^ 1);
            __syncthreads();
            buf ^= 1;
        }
    }

    int NP = N >> 1;
#pragma unroll
    for (int mt = 0; mt < 2; mt++) {
        int rbase = row0 + wm * 32 + mt * 16;
#pragma unroll
        for (int nt = 0; nt < 4; nt++) {
            int cb = col0 + wn * 32 + nt * 8 + 2 * tig;
            float b0 = (cb < N) ? bias[cb] : 0.f;
            float b1 = (cb + 1 < N) ? bias[cb + 1] : 0.f;
#pragma unroll
            for (int half = 0; half < 2; half++) {
                int r = rbase + g + half * 8;
                float v0 = acc[mt][nt][half * 2 + 0] + b0;
                float v1 = acc[mt][nt][half * 2 + 1] + b1;
                if (relu) { v0 = fmaxf(v0, 0.f); v1 = fmaxf(v1, 0.f); }
                if (C) {
                    if (cb < N)     C[(size_t)r * ldc + cb]     = v0;
                    if (cb + 1 < N) C[(size_t)r * ldc + cb + 1] = v1;
                }
                if (Chl && cb + 1 < N)
                    Chl[(size_t)r * NP + (cb >> 1)] = split2(v0, v1);
            }
        }
    }
}

// ---------------- attention part 1: scores (lower-tri tiles) ----------------
__global__ __launch_bounds__(256)
void score_kernel(const float* __restrict__ Q, int qld,
                  const float* __restrict__ Kp, int kld,
                  float* __restrict__ S)
{
    int bx = blockIdx.x, by = blockIdx.y;
    if (bx > by) return;
    int z = blockIdx.z;
    int b = z >> 3, h = z & 7;
    __shared__ float Qs[64][68];
    __shared__ float Ks[64][68];
    int tid = threadIdx.x;
    const float* Qbase = Q  + (size_t)(b * Sq + by * 64) * qld + h * DK;
    const float* Kbase = Kp + (size_t)(b * Sq + bx * 64) * kld + h * DK;
#pragma unroll
    for (int l = 0; l < 4; l++) {
        int idx = tid + l * 256;
        int r = idx >> 4, c4 = (idx & 15) * 4;
        float4 q4 = *(const float4*)(Qbase + (size_t)r * qld + c4);
        Qs[c4 + 0][r] = q4.x; Qs[c4 + 1][r] = q4.y;
        Qs[c4 + 2][r] = q4.z; Qs[c4 + 3][r] = q4.w;
        float4 k4 = *(const float4*)(Kbase + (size_t)r * kld + c4);
        Ks[c4 + 0][r] = k4.x; Ks[c4 + 1][r] = k4.y;
        Ks[c4 + 2][r] = k4.z; Ks[c4 + 3][r] = k4.w;
    }
    __syncthreads();
    int tx = tid & 15, ty = tid >> 4;
    float acc[4][4];
#pragma unroll
    for (int i = 0; i < 4; i++)
#pragma unroll
        for (int j = 0; j < 4; j++) acc[i][j] = 0.f;
#pragma unroll 8
    for (int d = 0; d < 64; d++) {
        float4 a4 = *(const float4*)&Qs[d][ty * 4];
        float4 b4 = *(const float4*)&Ks[d][tx * 4];
        float a[4] = {a4.x, a4.y, a4.z, a4.w};
        float b[4] = {b4.x, b4.y, b4.z, b4.w};
#pragma unroll
        for (int i = 0; i < 4; i++)
#pragma unroll
            for (int j = 0; j < 4; j++) acc[i][j] = fmaf(a[i], b[j], acc[i][j]);
    }
    float* Srow = S + ((size_t)z * Sq + by * 64) * Sq + bx * 64;
#pragma unroll
    for (int i = 0; i < 4; i++)
#pragma unroll
        for (int j = 0; j < 4; j++)
            Srow[(size_t)(ty * 4 + i) * Sq + tx * 4 + j] = acc[i][j] * 0.125f;
}

// ---------------- attention part 2: register-resident softmax/decay ---------
__global__ __launch_bounds__(256)
void decay_softmax_kernel(float* __restrict__ S, const float* __restrict__ gammas,
                          int layer, int strict)
{
    __shared__ float shw[8];
    __shared__ float shpre[8];
    __shared__ float shb;
    int i = blockIdx.x, z = blockIdx.y, h = z & 7;
    int tid = threadIdx.x, lane = tid & 31, wid = tid >> 5;
    float* row = S + ((size_t)z * Sq + i) * Sq;
    int kmax = i - strict;
    int k0 = 2 * tid, k1 = 2 * tid + 1;
    if (kmax < 0) {
        *(float2*)&row[k0] = make_float2(0.f, 0.f);
        return;
    }
    float2 rw = *(const float2*)&row[k0];
    float s0 = rw.x, s1 = rw.y;
    bool v0 = (k0 <= kmax), v1 = (k1 <= kmax);

    float lm = fmaxf(v0 ? s0 : -3e38f, v1 ? s1 : -3e38f);
#pragma unroll
    for (int o = 16; o; o >>= 1) lm = fmaxf(lm, __shfl_xor_sync(~0u, lm, o));
    if (lane == 0) shw[wid] = lm;
    __syncthreads();
    if (tid == 0) {
        float m = shw[0];
#pragma unroll
        for (int w = 1; w < 8; w++) m = fmaxf(m, shw[w]);
        shb = m;
    }
    __syncthreads();
    float m1 = shb;

    float p0 = v0 ? expf(s0 - m1) : 0.f;
    float p1 = v1 ? expf(s1 - m1) : 0.f;

    float ls = p0 + p1;
#pragma unroll
    for (int o = 16; o; o >>= 1) ls += __shfl_xor_sync(~0u, ls, o);
    if (lane == 0) shw[wid] = ls;
    __syncthreads();
    if (tid == 0) {
        float m = 0.f;
#pragma unroll
        for (int w = 0; w < 8; w++) m += shw[w];
        shb = m;
    }
    __syncthreads();
    float inv1 = 1.f / shb;
    p0 *= inv1; p1 *= inv1;

    float s = p0 + p1;
#pragma unroll
    for (int o = 1; o < 32; o <<= 1) {
        float t = __shfl_up_sync(~0u, s, o);
        if (lane >= o) s += t;
    }
    if (lane == 31) shw[wid] = s;
    __syncthreads();
    if (wid == 0 && lane < 8) {
        float t = shw[lane];
#pragma unroll
        for (int o = 1; o < 8; o <<= 1) {
            float tt = __shfl_up_sync(0xffu, t, o);
            if (lane >= o) t += tt;
        }
        shpre[lane] = t;
    }
    __syncthreads();
    float base = wid ? shpre[wid - 1] : 0.f;
    float cum1 = base + s;
    float cum0 = cum1 - p1;
    float total = shpre[7];

    float gm = gammas[layer * Hh + h];
    float sp = (gm > 20.f) ? gm : log1pf(expf(gm));
    float gamma = -sp;

    float suf0 = total - cum0, suf1 = total - cum1;
    float d0 = sqrtf(fmaxf(suf0 * (float)(i - k0), 0.f));
    float d1 = sqrtf(fmaxf(suf1 * (float)(i - k1), 0.f));
    float te0 = fminf(fmaxf(expf(d0 * gamma), 1e-5f), 1e5f);
    float te1 = fminf(fmaxf(expf(d1 * gamma), 1e-5f), 1e5f);
    float t0 = s0 * te0, t1 = s1 * te1;

    lm = fmaxf(v0 ? t0 : -3e38f, v1 ? t1 : -3e38f);
#pragma unroll
    for (int o = 16; o; o >>= 1) lm = fmaxf(lm, __shfl_xor_sync(~0u, lm, o));
    if (lane == 0) shw[wid] = lm;
    __syncthreads();
    if (tid == 0) {
        float m = shw[0];
#pragma unroll
        for (int w = 1; w < 8; w++) m = fmaxf(m, shw[w]);
        shb = m;
    }
    __syncthreads();
    float m2 = shb;

    float q0 = v0 ? expf(t0 - m2) : 0.f;
    float q1 = v1 ? expf(t1 - m2) : 0.f;

    ls = q0 + q1;
#pragma unroll
    for (int o = 16; o; o >>= 1) ls += __shfl_xor_sync(~0u, ls, o);
    if (lane == 0) shw[wid] = ls;
    __syncthreads();
    if (tid == 0) {
        float m = 0.f;
#pragma unroll
        for (int w = 0; w < 8; w++) m += shw[w];
        shb = m;
    }
    __syncthreads();
    float inv2 = 1.f / shb;

    *(float2*)&row[k0] = make_float2(q0 * inv2, q1 * inv2);
}

// ---------------- attention part 3: O = P @ V (writes split Ab) -------------
__global__ __launch_bounds__(256)
void av_kernel(const float* __restrict__ S, const float* __restrict__ V, int vld,
               uint2* __restrict__ Abs)
{
    int qt = blockIdx.x, z = blockIdx.y;
    int b = z >> 3, h = z & 7;
    __shared__ float Ps[16][68];
    __shared__ float Vs[16][68];
    int tid = threadIdx.x, tx = tid & 15, ty = tid >> 4;
    float acc[4][4];
#pragma unroll
    for (int i = 0; i < 4; i++)
#pragma unroll
        for (int j = 0; j < 4; j++) acc[i][j] = 0.f;

    const float* Srow  = S + ((size_t)z * Sq + qt * 64) * Sq;
    const float* Vbase = V + (size_t)b * Sq * vld + h * DK;
    int nkt = qt * 4 + 4;
    for (int kt = 0; kt < nkt; kt++) {
        int k0 = kt * 16;
        {
            int q = tid >> 2, kc = (tid & 3) * 4;
            float4 p4 = *(const float4*)(Srow + (size_t)q * Sq + k0 + kc);
            Ps[kc + 0][q] = p4.x; Ps[kc + 1][q] = p4.y;
            Ps[kc + 2][q] = p4.z; Ps[kc + 3][q] = p4.w;
            int kr = tid >> 4, d4 = (tid & 15) * 4;
            *(float4*)&Vs[kr][d4] = *(const float4*)(Vbase + (size_t)(k0 + kr) * vld + d4);
        }
        __syncthreads();
#pragma unroll
        for (int kk = 0; kk < 16; kk++) {
            float4 a4 = *(const float4*)&Ps[kk][ty * 4];
            float4 b4 = *(const float4*)&Vs[kk][tx * 4];
            float a[4] = {a4.x, a4.y, a4.z, a4.w};
            float b[4] = {b4.x, b4.y, b4.z, b4.w};
#pragma unroll
            for (int i = 0; i < 4; i++)
#pragma unroll
                for (int j = 0; j < 4; j++) acc[i][j] = fmaf(a[i], b[j], acc[i][j]);
        }
        __syncthreads();
    }
#pragma unroll
    for (int i = 0; i < 4; i++) {
        size_t r = (size_t)(b * Sq + qt * 64 + ty * 4 + i);
        int cp = (h * DK + tx * 4) >> 1;
        Abs[r * 256 + cp]     = split2(acc[i][0], acc[i][1]);
        Abs[r * 256 + cp + 1] = split2(acc[i][2], acc[i][3]);
    }
}

// ---------------- residual + LayerNorm (writes fp32 + split) ----------------
__global__ void ln_add_kernel(const float* __restrict__ A, const float* __restrict__ Bv,
                              const float* __restrict__ sc, const float* __restrict__ bi,
                              float* __restrict__ out, uint2* __restrict__ outs)
{
    int r = blockIdx.x, tid = threadIdx.x;
    int c0 = tid * 4;
    const float* a  = A  + (size_t)r * Dm;
    const float* bq = Bv + (size_t)r * Dm;
    float4 a4 = *(const float4*)&a[c0];
    float4 b4 = *(const float4*)&bq[c0];
    float v[4] = {a4.x + b4.x, a4.y + b4.y, a4.z + b4.z, a4.w + b4.w};
    float s = v[0] + v[1] + v[2] + v[3];
    float s2 = v[0]*v[0] + v[1]*v[1] + v[2]*v[2] + v[3]*v[3];
    __shared__ float rs[4], rs2[4];
#pragma unroll
    for (int o = 16; o > 0; o >>= 1) {
        s  += __shfl_down_sync(0xffffffffu, s,  o);
        s2 += __shfl_down_sync(0xffffffffu, s2, o);
    }
    int w = tid >> 5, l = tid & 31;
    if (l == 0) { rs[w] = s; rs2[w] = s2; }
    __syncthreads();
    float ss  = rs[0] + rs[1] + rs[2] + rs[3];
    float ss2 = rs2[0] + rs2[1] + rs2[2] + rs2[3];
    float mean = ss / 512.f;
    float var  = ss2 / 512.f - mean * mean;
    float rstd = rsqrtf(var + 1e-5f);
    float4 sc4 = *(const float4*)&sc[c0];
    float4 bi4 = *(const float4*)&bi[c0];
    float o0 = (v[0] - mean) * rstd * sc4.x + bi4.x;
    float o1 = (v[1] - mean) * rstd * sc4.y + bi4.y;
    float o2 = (v[2] - mean) * rstd * sc4.z + bi4.z;
    float o3 = (v[3] - mean) * rstd * sc4.w + bi4.w;
    *(float4*)&out[(size_t)r * Dm + c0] = make_float4(o0, o1, o2, o3);
    size_t sb = (size_t)r * 256 + (c0 >> 1);
    outs[sb]     = split2(o0, o1);
    outs[sb + 1] = split2(o2, o3);
}

// ---------------- concat splits: Ccs = [xs | x0s] ----------------
__global__ void concat_kernel(const uint2* __restrict__ xs, const uint2* __restrict__ x0s,
                              uint2* __restrict__ Ccs)
{
    int r = blockIdx.x;
    int u = threadIdx.x;                  // 256 threads
    Ccs[(size_t)r * 512 + u]       = xs [(size_t)r * 256 + u];
    Ccs[(size_t)r * 512 + 256 + u] = x0s[(size_t)r * 256 + u];
}

// ---------------- host ----------------
static inline void gemmHL(const uint2* A, const uint2* W, int ldw, const float* bias,
                          float* C, int ldc, uint2* Chl, int M, int N, int K, int relu)
{
    dim3 grid((N + 127) / 128, M / 128);
    gemm_hl<<<grid, 512>>>(A, W, ldw, bias, C, ldc, Chl, M, N, K, relu);
}

extern "C" void kernel_launch(void* const* d_in, const int* in_sizes, int n_in,
                              void* d_out, int out_size)
{
    const int*   c_data  = (const int*)  d_in[0];
    const int*   ca_data = (const int*)  d_in[1];
    const float* c_emb   = (const float*)d_in[2];
    const float* ca_emb  = (const float*)d_in[3];
    const float* Wk      = (const float*)d_in[4];
    const float* bk      = (const float*)d_in[5];
    const float* Wv      = (const float*)d_in[6];
    const float* bv      = (const float*)d_in[7];
    const float* Wo      = (const float*)d_in[8];
    const float* bo      = (const float*)d_in[9];
    const float* gammas  = (const float*)d_in[10];
    const float* ln1s    = (const float*)d_in[11];
    const float* ln1b    = (const float*)d_in[12];
    const float* W1      = (const float*)d_in[13];
    const float* b1      = (const float*)d_in[14];
    const float* W2      = (const float*)d_in[15];
    const float* b2      = (const float*)d_in[16];
    const float* ln2s    = (const float*)d_in[17];
    const float* ln2b    = (const float*)d_in[18];
    const float* oW0     = (const float*)d_in[19];
    const float* ob0     = (const float*)d_in[20];
    const float* oW1     = (const float*)d_in[21];
    const float* ob1     = (const float*)d_in[22];
    const float* oW2     = (const float*)d_in[23];
    const float* ob2     = (const float*)d_in[24];
    float* out = (float*)d_out;

    float *x0, *y, *x, *QV, *Kb, *Ob, *T1, *Sb, *bqv;
    uint2 *x0s, *ys, *xs, *T1s, *Abs, *Hfs, *Ccs, *M1s, *M2s;
    uint2 *Wqvs, *Wos, *W1s, *W2s, *oW0s, *oW1s, *oW2s;
    cudaGetSymbolAddress((void**)&x0, g_x0);
    cudaGetSymbolAddress((void**)&y,  g_y);
    cudaGetSymbolAddress((void**)&x,  g_x);
    cudaGetSymbolAddress((void**)&QV, g_QV);
    cudaGetSymbolAddress((void**)&Kb, g_K);
    cudaGetSymbolAddress((void**)&Ob, g_Ob);
    cudaGetSymbolAddress((void**)&T1, g_T1);
    cudaGetSymbolAddress((void**)&Sb, g_S);
    cudaGetSymbolAddress((void**)&bqv, g_bqv);
    cudaGetSymbolAddress((void**)&x0s, g_x0s);
    cudaGetSymbolAddress((void**)&ys,  g_ys);
    cudaGetSymbolAddress((void**)&xs,  g_xs);
    cudaGetSymbolAddress((void**)&T1s, g_T1s);
    cudaGetSymbolAddress((void**)&Abs, g_Abs);
    cudaGetSymbolAddress((void**)&Hfs, g_Hfs);
    cudaGetSymbolAddress((void**)&Ccs, g_Ccs);
    cudaGetSymbolAddress((void**)&M1s, g_M1s);
    cudaGetSymbolAddress((void**)&M2s, g_M2s);
    cudaGetSymbolAddress((void**)&Wqvs, g_Wqvs);
    cudaGetSymbolAddress((void**)&Wos,  g_Wos);
    cudaGetSymbolAddress((void**)&W1s,  g_W1s);
    cudaGetSymbolAddress((void**)&W2s,  g_W2s);
    cudaGetSymbolAddress((void**)&oW0s, g_oW0s);
    cudaGetSymbolAddress((void**)&oW1s, g_oW1s);
    cudaGetSymbolAddress((void**)&oW2s, g_oW2s);

    // ---- weight prep (every call; deterministic) ----
    split_w<<<dim3(512,1,6), 256>>>(Wk, Wqvs, 512, 512, 1024, 0,   (size_t)512*512, (size_t)256*1024);
    split_w<<<dim3(512,1,6), 256>>>(Wv, Wqvs, 512, 512, 1024, 512, (size_t)512*512, (size_t)256*1024);
    split_w<<<dim3(512,1,6), 256>>>(Wo, Wos,  512, 512, 512,  0,   (size_t)512*512, (size_t)256*512);
    split_w<<<dim3(2048,1,6),256>>>(W1, W1s,  512, 2048, 2048,0,   (size_t)512*2048,(size_t)256*2048);
    split_w<<<dim3(2048,1,6),256>>>(W2, W2s,  2048,512,  512, 0,   (size_t)2048*512,(size_t)1024*512);
    split_w<<<dim3(1024,1,1),256>>>(oW0, oW0s, 1024, 512, 512, 0, 0, 0);
    split_w<<<dim3(1024,1,1),256>>>(oW1, oW1s, 512, 1024, 1024, 0, 0, 0);
    split_w<<<dim3(2000,1,1),256>>>(oW2, oW2s, 1024, 1000, 1000, 0, 0, 0);
    pack_bqv<<<24, 256>>>(bk, bv, bqv);

    embed_kernel<<<MTOK, 128>>>(c_data, ca_data, c_emb, ca_emb, x0, y, x, x0s, ys, xs);

    for (int li = 0; li < 6; li++) {
        int strict, ap;
        float* qio; uint2* qios;
        const float* Kp; int kld;
        uint2* Wqv_i = Wqvs + (size_t)li * 256 * 1024;

        if (li < 2) {
            strict = 0; ap = 1; qio = y; qios = ys;
            // K = Wk(x0)
            gemmHL(x0s, Wqv_i, 1024, bk + li*512, Kb, 512, nullptr, MTOK, 512, 512, 0);
            // QV = [Wk|Wv](y)
            gemmHL(ys, Wqv_i, 1024, bqv + li*1024, QV, 1024, nullptr, MTOK, 1024, 512, 0);
            Kp = Kb; kld = 512;
        } else {
            int j = li - 2;
            qio = x; qios = xs;
            if ((j & 1) == 0) {
                strict = 0; ap = 0;
                gemmHL(xs, Wqv_i, 1024, bqv + li*1024, QV, 1024, nullptr, MTOK, 1024, 512, 0);
            } else {
                strict = 1; ap = 1;
                gemmHL(xs, Wqv_i, 1024, bk + li*512, QV, 1024, nullptr, MTOK, 512, 512, 0);       // Q=K
                gemmHL(ys, Wqv_i + 512, 1024, bv + li*512, QV + 512, 1024, nullptr, MTOK, 512, 512, 0); // V from y
            }
            Kp = QV; kld = 1024;
        }

        score_kernel<<<dim3(8, 8, NBH), 256>>>(QV, 1024, Kp, kld, Sb);
        decay_softmax_kernel<<<dim3(Sq, NBH), 256>>>(Sb, gammas, li, strict);
        av_kernel<<<dim3(8, NBH), 256>>>(Sb, QV + 512, 1024, Abs);

        gemmHL(Abs, Wos + (size_t)li * 256 * 512, 512, bo + li*512, Ob, 512, nullptr, MTOK, 512, 512, 0);
        ln_add_kernel<<<MTOK, 128>>>(qio, Ob, ln1s + li*Dm, ln1b + li*Dm,
                                     ap ? T1 : qio, ap ? T1s : qios);
        if (ap) {
            gemmHL(T1s, W1s + (size_t)li * 256 * 2048, 2048, b1 + li*FF,
                   nullptr, 0, Hfs, MTOK, 2048, 512, 1);
            gemmHL(Hfs, W2s + (size_t)li * 1024 * 512, 512, b2 + li*512,
                   Ob, 512, nullptr, MTOK, 512, 2048, 0);
            ln_add_kernel<<<MTOK, 128>>>(T1, Ob, ln2s + li*Dm, ln2b + li*Dm, qio, qios);
        }
    }

    concat_kernel<<<MTOK, 256>>>(xs, x0s, Ccs);
    gemmHL(Ccs, oW0s, 512,  ob0, nullptr, 0, M1s, MTOK, 512,  1024, 1);
    gemmHL(M1s, oW1s, 1024, ob1, nullptr, 0, M2s, MTOK, 1024, 512,  1);
    gemmHL(M2s, oW2s, 1000, ob2, out, 1000, nullptr, MTOK, 1000, 1024, 0);
}

// round 8
// speedup vs baseline: 1.8692x; 1.0693x over previous
#include <cuda_runtime.h>
#include <cuda_bf16.h>
#include <math.h>
#include <stdint.h>

#define Bsz 8
#define Sq  512
#define Dm  512
#define Hh  8
#define DK  64
#define FF  2048
#define MTOK (Bsz*Sq)   // 4096
#define NCPT 1000
#define NBH (Bsz*Hh)    // 64

// ---------------- scratch (device globals; no allocation) ----------------
__device__ float g_y [MTOK*Dm];
__device__ float g_x [MTOK*Dm];
__device__ float g_QV[MTOK*1024];
__device__ float g_Ob[MTOK*Dm];
__device__ float g_T1[MTOK*Dm];
__device__ float g_S [NBH*Sq*Sq];          // 64 MB scores
__device__ float g_bqv[6*1024];
// split (hi/lo bf16 pair-packed) activations: uint2 per k-pair
__device__ uint2 g_x0s[MTOK*256];
__device__ uint2 g_ys [MTOK*256];
__device__ uint2 g_xs [MTOK*256];
__device__ uint2 g_T1s[MTOK*256];
__device__ uint2 g_Abs[MTOK*256];
__device__ uint2 g_Hfs[MTOK*1024];
__device__ uint2 g_Ccs[MTOK*512];
__device__ uint2 g_M1s[MTOK*256];
__device__ uint2 g_M2s[MTOK*512];
__device__ uint2 g_QVs[MTOK*512];          // split Q|V (Q part used)
__device__ uint2 g_Ks [MTOK*256];          // split K (layers 0-1)
__device__ uint2 g_Vts[NBH*64*256];        // split V^T per (b,h): [d][seq-pair]
// split weights (k-pair packed [K/2][N])
__device__ uint2 g_Wqvs[6*256*1024];
__device__ uint2 g_Wos [6*256*512];
__device__ uint2 g_W1s [6*256*2048];
__device__ uint2 g_W2s [6*1024*512];
__device__ uint2 g_oW0s[512*512];
__device__ uint2 g_oW1s[256*1024];
__device__ uint2 g_oW2s[512*1000];

// ---------------- split helper ----------------
__device__ __forceinline__ uint2 split2(float v0, float v1) {
    __nv_bfloat16 h0 = __float2bfloat16(v0);
    __nv_bfloat16 h1 = __float2bfloat16(v1);
    float r0 = v0 - __bfloat162float(h0);
    float r1 = v1 - __bfloat162float(h1);
    __nv_bfloat162 hh; hh.x = h0; hh.y = h1;
    __nv_bfloat162 ll = __floats2bfloat162_rn(r0, r1);
    return make_uint2(*(uint32_t*)&hh, *(uint32_t*)&ll);
}
__device__ __forceinline__ void mma_bf16(float* c, const uint32_t* a, const uint32_t* b) {
    asm volatile(
        "mma.sync.aligned.m16n8k16.row.col.f32.bf16.bf16.f32 "
        "{%0,%1,%2,%3}, {%4,%5,%6,%7}, {%8,%9}, {%0,%1,%2,%3};"
        : "+f"(c[0]), "+f"(c[1]), "+f"(c[2]), "+f"(c[3])
        : "r"(a[0]), "r"(a[1]), "r"(a[2]), "r"(a[3]), "r"(b[0]), "r"(b[1]));
}

// ---------------- weight split: W[K][N] fp32 -> out[K/2][ldo] uint2 ----------
__global__ void split_w(const float* __restrict__ W, uint2* __restrict__ out,
                        int K, int N, int ldo, int colOff,
                        size_t inStride, size_t outStride)
{
    int z = blockIdx.z;
    const float* Wz = W + (size_t)z * inStride;
    uint2* oz = out + (size_t)z * outStride + colOff;
    int KP = K >> 1;
    int total = KP * N;
    for (int idx = blockIdx.x * blockDim.x + threadIdx.x; idx < total;
         idx += gridDim.x * blockDim.x) {
        int kp = idx / N, n = idx - kp * N;
        float v0 = Wz[(size_t)(2 * kp) * N + n];
        float v1 = Wz[(size_t)(2 * kp + 1) * N + n];
        oz[(size_t)kp * ldo + n] = split2(v0, v1);
    }
}

__global__ void pack_bqv(const float* __restrict__ bk, const float* __restrict__ bv,
                         float* __restrict__ bqv)
{
    int i = blockIdx.x * blockDim.x + threadIdx.x;
    if (i >= 6 * 1024) return;
    int li = i >> 10, j = i & 1023;
    bqv[i] = (j < 512) ? bk[li * 512 + j] : bv[li * 512 + j - 512];
}

// ---------------- embed ----------------
__global__ void embed_kernel(const int* __restrict__ c_data, const int* __restrict__ ca_data,
                             const float* __restrict__ c_emb, const float* __restrict__ ca_emb,
                             float* __restrict__ y, float* __restrict__ x,
                             uint2* __restrict__ x0s, uint2* __restrict__ ys, uint2* __restrict__ xs)
{
    int r = blockIdx.x;
    int c = c_data[r];
    int resp = (ca_data[r] - c) / NCPT;
    const float* er = c_emb + (size_t)c * Dm;
    const float* ar = ca_emb + (size_t)resp * Dm;
    int j = threadIdx.x * 4;
    float4 e4 = *(const float4*)(er + j);
    float4 a4 = *(const float4*)(ar + j);
    float y0 = e4.x + a4.x, y1 = e4.y + a4.y, y2 = e4.z + a4.z, y3 = e4.w + a4.w;
    *(float4*)&x[(size_t)r*Dm + j] = e4;
    *(float4*)&y[(size_t)r*Dm + j] = make_float4(y0, y1, y2, y3);
    size_t sb = (size_t)r * 256 + (j >> 1);
    uint2 s0 = split2(e4.x, e4.y), s1 = split2(e4.z, e4.w);
    x0s[sb] = s0; x0s[sb + 1] = s1;
    xs [sb] = s0; xs [sb + 1] = s1;
    ys [sb] = split2(y0, y1); ys[sb + 1] = split2(y2, y3);
}

// ---------------- bf16x3 tensor-core GEMM, pre-split operands ---------------
#define GP 138

__global__ __launch_bounds__(512)
void gemm_hl(const uint2* __restrict__ Ahl, const uint2* __restrict__ Whl, int ldw,
             const float* __restrict__ bias, float* __restrict__ C, int ldc,
             uint2* __restrict__ Chl, int ldch,
             int M, int N, int K, int relu)
{
    __shared__ uint2 As[2][8][GP];
    __shared__ uint2 Bs[2][8][GP];

    int tid = threadIdx.x;
    int row0 = blockIdx.y * 128, col0 = blockIdx.x * 128;
    int warp = tid >> 5, lane = tid & 31;
    int wm = warp & 3, wn = warp >> 2;      // 4x4 warps, 32x32 tiles
    int g = lane >> 2, tig = lane & 3;

    bool isA = tid < 256;
    int arow = (tid & 255) >> 1;
    int aks = tid & 1;
    int bn = tid & 127;
    int bks = (tid >> 7) & 1;
    int KP = K >> 1;
    const uint2* Ap = Ahl + (size_t)(row0 + arow) * KP + aks * 4;
    int bcg = col0 + bn;
    bool bok = bcg < N;

    float acc[2][4][4];
#pragma unroll
    for (int i = 0; i < 2; i++)
#pragma unroll
        for (int j = 0; j < 4; j++)
#pragma unroll
            for (int q = 0; q < 4; q++) acc[i][j][q] = 0.f;

    uint2 rv[4];
    int T = K >> 4;

    auto ldg = [&](int t) {
        if (isA) {
            const uint2* p = Ap + t * 8;
            uint4 u0 = *(const uint4*)p;
            uint4 u1 = *(const uint4*)(p + 2);
            rv[0] = make_uint2(u0.x, u0.y); rv[1] = make_uint2(u0.z, u0.w);
            rv[2] = make_uint2(u1.x, u1.y); rv[3] = make_uint2(u1.z, u1.w);
        } else {
            const uint2* p = Whl + (size_t)(t * 8 + bks * 4) * ldw + bcg;
#pragma unroll
            for (int j = 0; j < 4; j++) rv[j] = bok ? p[(size_t)j * ldw] : make_uint2(0, 0);
        }
    };
    auto sts = [&](int bf) {
        int ks = isA ? aks : bks;
        int r  = isA ? arow : bn;
        uint2 (*dst)[GP] = isA ? As[bf] : Bs[bf];
#pragma unroll
        for (int jj = 0; jj < 4; jj++) dst[jj * 2 + ks][r] = rv[jj];
    };

    ldg(0); sts(0);
    __syncthreads();

    int buf = 0;
    for (int t = 0; t < T; t++) {
        if (t + 1 < T) ldg(t + 1);
        uint32_t ah[2][4], al[2][4];
#pragma unroll
        for (int mt = 0; mt < 2; mt++) {
            int r = wm * 32 + mt * 16 + g;
            uint2 ua = As[buf][2*tig    ][r];
            uint2 ub = As[buf][2*tig    ][r + 8];
            uint2 uc = As[buf][2*tig + 1][r];
            uint2 ud = As[buf][2*tig + 1][r + 8];
            ah[mt][0]=ua.x; ah[mt][1]=ub.x; ah[mt][2]=uc.x; ah[mt][3]=ud.x;
            al[mt][0]=ua.y; al[mt][1]=ub.y; al[mt][2]=uc.y; al[mt][3]=ud.y;
        }
#pragma unroll
        for (int nt = 0; nt < 4; nt++) {
            int n0 = wn * 32 + nt * 8 + g;
            uint2 u0 = Bs[buf][2*tig    ][n0];
            uint2 u1 = Bs[buf][2*tig + 1][n0];
            uint32_t bh[2] = {u0.x, u1.x};
            uint32_t bl[2] = {u0.y, u1.y};
#pragma unroll
            for (int mt = 0; mt < 2; mt++) {
                mma_bf16(acc[mt][nt], ah[mt], bh);
                mma_bf16(acc[mt][nt], al[mt], bh);
                mma_bf16(acc[mt][nt], ah[mt], bl);
            }
        }
        if (t + 1 < T) {
            sts(buf ^ 1);
            __syncthreads();
            buf ^= 1;
        }
    }

#pragma unroll
    for (int mt = 0; mt < 2; mt++) {
        int rbase = row0 + wm * 32 + mt * 16;
#pragma unroll
        for (int nt = 0; nt < 4; nt++) {
            int cb = col0 + wn * 32 + nt * 8 + 2 * tig;
            float b0 = (cb < N) ? bias[cb] : 0.f;
            float b1 = (cb + 1 < N) ? bias[cb + 1] : 0.f;
#pragma unroll
            for (int half = 0; half < 2; half++) {
                int r = rbase + g + half * 8;
                float v0 = acc[mt][nt][half * 2 + 0] + b0;
                float v1 = acc[mt][nt][half * 2 + 1] + b1;
                if (relu) { v0 = fmaxf(v0, 0.f); v1 = fmaxf(v1, 0.f); }
                if (C) {
                    if (cb < N)     C[(size_t)r * ldc + cb]     = v0;
                    if (cb + 1 < N) C[(size_t)r * ldc + cb + 1] = v1;
                }
                if (Chl && cb + 1 < N)
                    Chl[(size_t)r * ldch + (cb >> 1)] = split2(v0, v1);
            }
        }
    }
}

// ---------------- V transpose + split: Vt[z][d][seq-pair] -------------------
__global__ void vtsplit(const float* __restrict__ V, uint2* __restrict__ Vts)
{
    __shared__ float t[32][65];
    int z = blockIdx.y, b = z >> 3, h = z & 7;
    int s0 = blockIdx.x * 32;
    int tid = threadIdx.x;
    {
        int i = tid >> 3, fj = tid & 7;
        const float* src = V + (size_t)(b * Sq + s0 + i) * 1024 + h * 64 + fj * 8;
        float4 v0 = *(const float4*)src;
        float4 v1 = *(const float4*)(src + 4);
        t[i][fj*8+0] = v0.x; t[i][fj*8+1] = v0.y; t[i][fj*8+2] = v0.z; t[i][fj*8+3] = v0.w;
        t[i][fj*8+4] = v1.x; t[i][fj*8+5] = v1.y; t[i][fj*8+6] = v1.z; t[i][fj*8+7] = v1.w;
    }
    __syncthreads();
    int d = tid >> 2, q = tid & 3;
    uint2* dst = Vts + ((size_t)z * 64 + d) * 256 + (s0 >> 1);
#pragma unroll
    for (int j = 0; j < 4; j++) {
        int kp = q * 4 + j;
        dst[kp] = split2(t[2*kp][d], t[2*kp+1][d]);
    }
}

// ---------------- attention part 1: scores via tensor cores -----------------
#define SGP 130
#define SCORE_SMEM (2*4*8*SGP*(int)sizeof(uint2))
__global__ __launch_bounds__(512)
void score_tc(const uint2* __restrict__ Qs, int ldq,
              const uint2* __restrict__ Ks, int ldk,
              float* __restrict__ S)
{
    int kt = blockIdx.x, qt = blockIdx.y;
    if (kt > qt) return;
    int z = blockIdx.z, b = z >> 3, h = z & 7;
    extern __shared__ uint2 sm[];
    uint2 (*As)[8][SGP] = (uint2(*)[8][SGP])sm;
    uint2 (*Bs)[8][SGP] = (uint2(*)[8][SGP])(sm + 4*8*SGP);

    int tid = threadIdx.x;
    {
        int r = tid >> 2, quarter = tid & 3;
        const uint2* qa = Qs + (size_t)(b*Sq + qt*128 + r) * ldq + h*32 + quarter*8;
        const uint2* ka = Ks + (size_t)(b*Sq + kt*128 + r) * ldk + h*32 + quarter*8;
#pragma unroll
        for (int j = 0; j < 4; j++) {
            uint4 uq = *(const uint4*)(qa + 2*j);
            uint4 uk = *(const uint4*)(ka + 2*j);
            int m0 = 2*j, m1 = 2*j + 1;
            int sl0 = (m0 & 3)*2 + (m0 >> 2);
            int sl1 = (m1 & 3)*2 + (m1 >> 2);
            As[quarter][sl0][r] = make_uint2(uq.x, uq.y);
            As[quarter][sl1][r] = make_uint2(uq.z, uq.w);
            Bs[quarter][sl0][r] = make_uint2(uk.x, uk.y);
            Bs[quarter][sl1][r] = make_uint2(uk.z, uk.w);
        }
    }
    __syncthreads();

    int warp = tid >> 5, lane = tid & 31;
    int wm = warp & 3, wn = warp >> 2;
    int g = lane >> 2, tig = lane & 3;
    float acc[2][4][4];
#pragma unroll
    for (int i = 0; i < 2; i++)
#pragma unroll
        for (int j = 0; j < 4; j++)
#pragma unroll
            for (int q = 0; q < 4; q++) acc[i][j][q] = 0.f;

#pragma unroll
    for (int c = 0; c < 4; c++) {
        uint32_t ah[2][4], al[2][4];
#pragma unroll
        for (int mt = 0; mt < 2; mt++) {
            int r = wm * 32 + mt * 16 + g;
            uint2 ua = As[c][2*tig    ][r];
            uint2 ub = As[c][2*tig    ][r + 8];
            uint2 uc = As[c][2*tig + 1][r];
            uint2 ud = As[c][2*tig + 1][r + 8];
            ah[mt][0]=ua.x; ah[mt][1]=ub.x; ah[mt][2]=uc.x; ah[mt][3]=ud.x;
            al[mt][0]=ua.y; al[mt][1]=ub.y; al[mt][2]=uc.y; al[mt][3]=ud.y;
        }
#pragma unroll
        for (int nt = 0; nt < 4; nt++) {
            int n0 = wn * 32 + nt * 8 + g;
            uint2 u0 = Bs[c][2*tig    ][n0];
            uint2 u1 = Bs[c][2*tig + 1][n0];
            uint32_t bh[2] = {u0.x, u1.x};
            uint32_t bl[2] = {u0.y, u1.y};
#pragma unroll
            for (int mt = 0; mt < 2; mt++) {
                mma_bf16(acc[mt][nt], ah[mt], bh);
                mma_bf16(acc[mt][nt], al[mt], bh);
                mma_bf16(acc[mt][nt], ah[mt], bl);
            }
        }
    }

    float* Sbase = S + ((size_t)z * Sq + qt * 128) * Sq + kt * 128;
#pragma unroll
    for (int mt = 0; mt < 2; mt++)
#pragma unroll
        for (int nt = 0; nt < 4; nt++)
#pragma unroll
            for (int half = 0; half < 2; half++) {
                int row = wm * 32 + mt * 16 + g + half * 8;
                int col = wn * 32 + nt * 8 + 2 * tig;
                float2 v = make_float2(acc[mt][nt][half*2] * 0.125f,
                                       acc[mt][nt][half*2+1] * 0.125f);
                *(float2*)&Sbase[(size_t)row * Sq + col] = v;
            }
}

// ---------------- attention part 2: register-resident softmax/decay ---------
__global__ __launch_bounds__(256)
void decay_softmax_kernel(float* __restrict__ S, const float* __restrict__ gammas,
                          int layer, int strict)
{
    __shared__ float shw[8];
    __shared__ float shpre[8];
    __shared__ float shb;
    int i = blockIdx.x, z = blockIdx.y, h = z & 7;
    int tid = threadIdx.x, lane = tid & 31, wid = tid >> 5;
    float* row = S + ((size_t)z * Sq + i) * Sq;
    int kmax = i - strict;
    int k0 = 2 * tid, k1 = 2 * tid + 1;
    if (kmax < 0) {
        *(float2*)&row[k0] = make_float2(0.f, 0.f);
        return;
    }
    float2 rw = *(const float2*)&row[k0];
    float s0 = rw.x, s1 = rw.y;
    bool v0 = (k0 <= kmax), v1 = (k1 <= kmax);

    float lm = fmaxf(v0 ? s0 : -3e38f, v1 ? s1 : -3e38f);
#pragma unroll
    for (int o = 16; o; o >>= 1) lm = fmaxf(lm, __shfl_xor_sync(~0u, lm, o));
    if (lane == 0) shw[wid] = lm;
    __syncthreads();
    if (tid == 0) {
        float m = shw[0];
#pragma unroll
        for (int w = 1; w < 8; w++) m = fmaxf(m, shw[w]);
        shb = m;
    }
    __syncthreads();
    float m1 = shb;

    float p0 = v0 ? expf(s0 - m1) : 0.f;
    float p1 = v1 ? expf(s1 - m1) : 0.f;

    float ls = p0 + p1;
#pragma unroll
    for (int o = 16; o; o >>= 1) ls += __shfl_xor_sync(~0u, ls, o);
    if (lane == 0) shw[wid] = ls;
    __syncthreads();
    if (tid == 0) {
        float m = 0.f;
#pragma unroll
        for (int w = 0; w < 8; w++) m += shw[w];
        shb = m;
    }
    __syncthreads();
    float inv1 = 1.f / shb;
    p0 *= inv1; p1 *= inv1;

    float s = p0 + p1;
#pragma unroll
    for (int o = 1; o < 32; o <<= 1) {
        float t = __shfl_up_sync(~0u, s, o);
        if (lane >= o) s += t;
    }
    if (lane == 31) shw[wid] = s;
    __syncthreads();
    if (wid == 0 && lane < 8) {
        float t = shw[lane];
#pragma unroll
        for (int o = 1; o < 8; o <<= 1) {
            float tt = __shfl_up_sync(0xffu, t, o);
            if (lane >= o) t += tt;
        }
        shpre[lane] = t;
    }
    __syncthreads();
    float base = wid ? shpre[wid - 1] : 0.f;
    float cum1 = base + s;
    float cum0 = cum1 - p1;
    float total = shpre[7];

    float gm = gammas[layer * Hh + h];
    float sp = (gm > 20.f) ? gm : log1pf(expf(gm));
    float gamma = -sp;

    float suf0 = total - cum0, suf1 = total - cum1;
    float d0 = sqrtf(fmaxf(suf0 * (float)(i - k0), 0.f));
    float d1 = sqrtf(fmaxf(suf1 * (float)(i - k1), 0.f));
    float te0 = fminf(fmaxf(expf(d0 * gamma), 1e-5f), 1e5f);
    float te1 = fminf(fmaxf(expf(d1 * gamma), 1e-5f), 1e5f);
    float t0 = s0 * te0, t1 = s1 * te1;

    lm = fmaxf(v0 ? t0 : -3e38f, v1 ? t1 : -3e38f);
#pragma unroll
    for (int o = 16; o; o >>= 1) lm = fmaxf(lm, __shfl_xor_sync(~0u, lm, o));
    if (lane == 0) shw[wid] = lm;
    __syncthreads();
    if (tid == 0) {
        float m = shw[0];
#pragma unroll
        for (int w = 1; w < 8; w++) m = fmaxf(m, shw[w]);
        shb = m;
    }
    __syncthreads();
    float m2 = shb;

    float q0 = v0 ? expf(t0 - m2) : 0.f;
    float q1 = v1 ? expf(t1 - m2) : 0.f;

    ls = q0 + q1;
#pragma unroll
    for (int o = 16; o; o >>= 1) ls += __shfl_xor_sync(~0u, ls, o);
    if (lane == 0) shw[wid] = ls;
    __syncthreads();
    if (tid == 0) {
        float m = 0.f;
#pragma unroll
        for (int w = 0; w < 8; w++) m += shw[w];
        shb = m;
    }
    __syncthreads();
    float inv2 = 1.f / shb;

    *(float2*)&row[k0] = make_float2(q0 * inv2, q1 * inv2);
}

// ---------------- attention part 3: O = P @ V via tensor cores --------------
__global__ __launch_bounds__(256)
void av_tc(const float* __restrict__ S, const uint2* __restrict__ Vts,
           uint2* __restrict__ Abs)
{
    __shared__ uint2 As[2][8][130];
    __shared__ uint2 Bs[2][8][66];
    int qt = blockIdx.x, z = blockIdx.y, b = z >> 3, h = z & 7;
    int tid = threadIdx.x;
    int warp = tid >> 5, lane = tid & 31;
    int wm = warp & 3, wn = warp >> 2;     // 4x2, 32q x 32d
    int g = lane >> 2, tig = lane & 3;

    int ar = tid >> 1, ahalf = tid & 1;
    const float* Sbase = S + ((size_t)z * Sq + qt * 128 + ar) * Sq + ahalf * 8;
    int bd = tid & 63, bpr = tid >> 6;
    const uint2* Vbase = Vts + ((size_t)z * 64 + bd) * 256 + bpr * 2;

    int nT = (qt + 1) * 8;
    float2 fa[4]; uint4 bu;
    auto ldg = [&](int t) {
#pragma unroll
        for (int j = 0; j < 4; j++) fa[j] = *(const float2*)(Sbase + t * 16 + 2 * j);
        bu = *(const uint4*)(Vbase + (size_t)t * 8);
    };
    auto sts = [&](int bf) {
#pragma unroll
        for (int j = 0; j < 4; j++)
            As[bf][j * 2 + ahalf][ar] = split2(fa[j].x, fa[j].y);
        int m0 = bpr * 2, m1 = bpr * 2 + 1;
        Bs[bf][(m0 & 3)*2 + (m0 >> 2)][bd] = make_uint2(bu.x, bu.y);
        Bs[bf][(m1 & 3)*2 + (m1 >> 2)][bd] = make_uint2(bu.z, bu.w);
    };

    float acc[2][4][4];
#pragma unroll
    for (int i = 0; i < 2; i++)
#pragma unroll
        for (int j = 0; j < 4; j++)
#pragma unroll
            for (int q = 0; q < 4; q++) acc[i][j][q] = 0.f;

    ldg(0); sts(0);
    __syncthreads();
    int buf = 0;
    for (int t = 0; t < nT; t++) {
        if (t + 1 < nT) ldg(t + 1);
        uint32_t ah[2][4], al[2][4];
#pragma unroll
        for (int mt = 0; mt < 2; mt++) {
            int r = wm * 32 + mt * 16 + g;
            uint2 ua = As[buf][2*tig    ][r];
            uint2 ub = As[buf][2*tig    ][r + 8];
            uint2 uc = As[buf][2*tig + 1][r];
            uint2 ud = As[buf][2*tig + 1][r + 8];
            ah[mt][0]=ua.x; ah[mt][1]=ub.x; ah[mt][2]=uc.x; ah[mt][3]=ud.x;
            al[mt][0]=ua.y; al[mt][1]=ub.y; al[mt][2]=uc.y; al[mt][3]=ud.y;
        }
#pragma unroll
        for (int nt = 0; nt < 4; nt++) {
            int n0 = wn * 32 + nt * 8 + g;
            uint2 u0 = Bs[buf][2*tig    ][n0];
            uint2 u1 = Bs[buf][2*tig + 1][n0];
            uint32_t bh[2] = {u0.x, u1.x};
            uint32_t bl[2] = {u0.y, u1.y};
#pragma unroll
            for (int mt = 0; mt < 2; mt++) {
                mma_bf16(acc[mt][nt], ah[mt], bh);
                mma_bf16(acc[mt][nt], al[mt], bh);
                mma_bf16(acc[mt][nt], ah[mt], bl);
            }
        }
        if (t + 1 < nT) {
            sts(buf ^ 1);
            __syncthreads();
            buf ^= 1;
        }
    }

#pragma unroll
    for (int mt = 0; mt < 2; mt++)
#pragma unroll
        for (int nt = 0; nt < 4; nt++)
#pragma unroll
            for (int half = 0; half < 2; half++) {
                int row = b * Sq + qt * 128 + wm * 32 + mt * 16 + g + half * 8;
                int ch  = h * 64 + wn * 32 + nt * 8 + 2 * tig;
                Abs[(size_t)row * 256 + (ch >> 1)] =
                    split2(acc[mt][nt][half*2], acc[mt][nt][half*2+1]);
            }
}

// ---------------- residual + LayerNorm (fp32 + split out) ----------------
__global__ void ln_add_kernel(const float* __restrict__ A, const float* __restrict__ Bv,
                              const float* __restrict__ sc, const float* __restrict__ bi,
                              float* __restrict__ out, uint2* __restrict__ outs)
{
    int r = blockIdx.x, tid = threadIdx.x;
    int c0 = tid * 4;
    const float* a  = A  + (size_t)r * Dm;
    const float* bq = Bv + (size_t)r * Dm;
    float4 a4 = *(const float4*)&a[c0];
    float4 b4 = *(const float4*)&bq[c0];
    float v[4] = {a4.x + b4.x, a4.y + b4.y, a4.z + b4.z, a4.w + b4.w};
    float s = v[0] + v[1] + v[2] + v[3];
    float s2 = v[0]*v[0] + v[1]*v[1] + v[2]*v[2] + v[3]*v[3];
    __shared__ float rs[4], rs2[4];
#pragma unroll
    for (int o = 16; o > 0; o >>= 1) {
        s  += __shfl_down_sync(0xffffffffu, s,  o);
        s2 += __shfl_down_sync(0xffffffffu, s2, o);
    }
    int w = tid >> 5, l = tid & 31;
    if (l == 0) { rs[w] = s; rs2[w] = s2; }
    __syncthreads();
    float ss  = rs[0] + rs[1] + rs[2] + rs[3];
    float ss2 = rs2[0] + rs2[1] + rs2[2] + rs2[3];
    float mean = ss / 512.f;
    float var  = ss2 / 512.f - mean * mean;
    float rstd = rsqrtf(var + 1e-5f);
    float4 sc4 = *(const float4*)&sc[c0];
    float4 bi4 = *(const float4*)&bi[c0];
    float o0 = (v[0] - mean) * rstd * sc4.x + bi4.x;
    float o1 = (v[1] - mean) * rstd * sc4.y + bi4.y;
    float o2 = (v[2] - mean) * rstd * sc4.z + bi4.z;
    float o3 = (v[3] - mean) * rstd * sc4.w + bi4.w;
    *(float4*)&out[(size_t)r * Dm + c0] = make_float4(o0, o1, o2, o3);
    size_t sb = (size_t)r * 256 + (c0 >> 1);
    outs[sb]     = split2(o0, o1);
    outs[sb + 1] = split2(o2, o3);
}

// ---------------- concat splits ----------------
__global__ void concat_kernel(const uint2* __restrict__ xs, const uint2* __restrict__ x0s,
                              uint2* __restrict__ Ccs)
{
    int r = blockIdx.x;
    int u = threadIdx.x;
    Ccs[(size_t)r * 512 + u]       = xs [(size_t)r * 256 + u];
    Ccs[(size_t)r * 512 + 256 + u] = x0s[(size_t)r * 256 + u];
}

// ---------------- host ----------------
static inline void gemmHL(const uint2* A, const uint2* W, int ldw, const float* bias,
                          float* C, int ldc, uint2* Chl, int ldch,
                          int M, int N, int K, int relu)
{
    dim3 grid((N + 127) / 128, M / 128);
    gemm_hl<<<grid, 512>>>(A, W, ldw, bias, C, ldc, Chl, ldch, M, N, K, relu);
}

extern "C" void kernel_launch(void* const* d_in, const int* in_sizes, int n_in,
                              void* d_out, int out_size)
{
    const int*   c_data  = (const int*)  d_in[0];
    const int*   ca_data = (const int*)  d_in[1];
    const float* c_emb   = (const float*)d_in[2];
    const float* ca_emb  = (const float*)d_in[3];
    const float* Wk      = (const float*)d_in[4];
    const float* bk      = (const float*)d_in[5];
    const float* Wv      = (const float*)d_in[6];
    const float* bv      = (const float*)d_in[7];
    const float* Wo      = (const float*)d_in[8];
    const float* bo      = (const float*)d_in[9];
    const float* gammas  = (const float*)d_in[10];
    const float* ln1s    = (const float*)d_in[11];
    const float* ln1b    = (const float*)d_in[12];
    const float* W1      = (const float*)d_in[13];
    const float* b1      = (const float*)d_in[14];
    const float* W2      = (const float*)d_in[15];
    const float* b2      = (const float*)d_in[16];
    const float* ln2s    = (const float*)d_in[17];
    const float* ln2b    = (const float*)d_in[18];
    const float* oW0     = (const float*)d_in[19];
    const float* ob0     = (const float*)d_in[20];
    const float* oW1     = (const float*)d_in[21];
    const float* ob1     = (const float*)d_in[22];
    const float* oW2     = (const float*)d_in[23];
    const float* ob2     = (const float*)d_in[24];
    float* out = (float*)d_out;

    cudaFuncSetAttribute(score_tc, cudaFuncAttributeMaxDynamicSharedMemorySize, SCORE_SMEM);

    float *y, *x, *QV, *Ob, *T1, *Sb, *bqv;
    cudaGetSymbolAddress((void**)&y,  g_y);
    cudaGetSymbolAddress((void**)&x,  g_x);
    cudaGetSymbolAddress((void**)&QV, g_QV);
    cudaGetSymbolAddress((void**)&Ob, g_Ob);
    cudaGetSymbolAddress((void**)&T1, g_T1);
    cudaGetSymbolAddress((void**)&Sb, g_S);
    cudaGetSymbolAddress((void**)&bqv, g_bqv);
    uint2 *x0s, *ys, *xs, *T1s, *Abs, *Hfs, *Ccs, *M1s, *M2s, *QVs, *Ks, *Vts;
    uint2 *Wqvs, *Wos, *W1s, *W2s, *oW0s, *oW1s, *oW2s;
    cudaGetSymbolAddress((void**)&x0s, g_x0s);
    cudaGetSymbolAddress((void**)&ys,  g_ys);
    cudaGetSymbolAddress((void**)&xs,  g_xs);
    cudaGetSymbolAddress((void**)&T1s, g_T1s);
    cudaGetSymbolAddress((void**)&Abs, g_Abs);
    cudaGetSymbolAddress((void**)&Hfs, g_Hfs);
    cudaGetSymbolAddress((void**)&Ccs, g_Ccs);
    cudaGetSymbolAddress((void**)&M1s, g_M1s);
    cudaGetSymbolAddress((void**)&M2s, g_M2s);
    cudaGetSymbolAddress((void**)&QVs, g_QVs);
    cudaGetSymbolAddress((void**)&Ks,  g_Ks);
    cudaGetSymbolAddress((void**)&Vts, g_Vts);
    cudaGetSymbolAddress((void**)&Wqvs, g_Wqvs);
    cudaGetSymbolAddress((void**)&Wos,  g_Wos);
    cudaGetSymbolAddress((void**)&W1s,  g_W1s);
    cudaGetSymbolAddress((void**)&W2s,  g_W2s);
    cudaGetSymbolAddress((void**)&oW0s, g_oW0s);
    cudaGetSymbolAddress((void**)&oW1s, g_oW1s);
    cudaGetSymbolAddress((void**)&oW2s, g_oW2s);

    // ---- weight prep ----
    split_w<<<dim3(512,1,6), 256>>>(Wk, Wqvs, 512, 512, 1024, 0,   (size_t)512*512, (size_t)256*1024);
    split_w<<<dim3(512,1,6), 256>>>(Wv, Wqvs, 512, 512, 1024, 512, (size_t)512*512, (size_t)256*1024);
    split_w<<<dim3(512,1,6), 256>>>(Wo, Wos,  512, 512, 512,  0,   (size_t)512*512, (size_t)256*512);
    split_w<<<dim3(2048,1,6),256>>>(W1, W1s,  512, 2048, 2048,0,   (size_t)512*2048,(size_t)256*2048);
    split_w<<<dim3(2048,1,6),256>>>(W2, W2s,  2048,512,  512, 0,   (size_t)2048*512,(size_t)1024*512);
    split_w<<<dim3(1024,1,1),256>>>(oW0, oW0s, 1024, 512, 512, 0, 0, 0);
    split_w<<<dim3(1024,1,1),256>>>(oW1, oW1s, 512, 1024, 1024, 0, 0, 0);
    split_w<<<dim3(2000,1,1),256>>>(oW2, oW2s, 1024, 1000, 1000, 0, 0, 0);
    pack_bqv<<<24, 256>>>(bk, bv, bqv);

    embed_kernel<<<MTOK, 128>>>(c_data, ca_data, c_emb, ca_emb, y, x, x0s, ys, xs);

    for (int li = 0; li < 6; li++) {
        int strict, ap;
        float* qio; uint2* qios;
        const uint2* Bspl; int ldk;
        uint2* Wqv_i = Wqvs + (size_t)li * 256 * 1024;

        if (li < 2) {
            strict = 0; ap = 1; qio = y; qios = ys;
            gemmHL(x0s, Wqv_i, 1024, bk + li*512, nullptr, 0, Ks, 256, MTOK, 512, 512, 0);
            gemmHL(ys, Wqv_i, 1024, bqv + li*1024, QV, 1024, QVs, 512, MTOK, 1024, 512, 0);
            Bspl = Ks; ldk = 256;
        } else {
            int j = li - 2;
            qio = x; qios = xs;
            if ((j & 1) == 0) {
                strict = 0; ap = 0;
                gemmHL(xs, Wqv_i, 1024, bqv + li*1024, QV, 1024, QVs, 512, MTOK, 1024, 512, 0);
            } else {
                strict = 1; ap = 1;
                gemmHL(xs, Wqv_i, 1024, bk + li*512, nullptr, 0, QVs, 512, MTOK, 512, 512, 0);
                gemmHL(ys, Wqv_i + 512, 1024, bv + li*512, QV + 512, 1024, nullptr, 0, MTOK, 512, 512, 0);
            }
            Bspl = QVs; ldk = 512;
        }

        vtsplit<<<dim3(16, NBH), 256>>>(QV + 512, Vts);
        score_tc<<<dim3(4, 4, NBH), 512, SCORE_SMEM>>>(QVs, 512, Bspl, ldk, Sb);
        decay_softmax_kernel<<<dim3(Sq, NBH), 256>>>(Sb, gammas, li, strict);
        av_tc<<<dim3(4, NBH), 256>>>(Sb, Vts, Abs);

        gemmHL(Abs, Wos + (size_t)li * 256 * 512, 512, bo + li*512, Ob, 512, nullptr, 0, MTOK, 512, 512, 0);
        ln_add_kernel<<<MTOK, 128>>>(qio, Ob, ln1s + li*Dm, ln1b + li*Dm,
                                     ap ? T1 : qio, ap ? T1s : qios);
        if (ap) {
            gemmHL(T1s, W1s + (size_t)li * 256 * 2048, 2048, b1 + li*FF,
                   nullptr, 0, Hfs, 1024, MTOK, 2048, 512, 1);
            gemmHL(Hfs, W2s + (size_t)li * 1024 * 512, 512, b2 + li*512,
                   Ob, 512, nullptr, 0, MTOK, 512, 2048, 0);
            ln_add_kernel<<<MTOK, 128>>>(T1, Ob, ln2s + li*Dm, ln2b + li*Dm, qio, qios);
        }
    }

    concat_kernel<<<MTOK, 256>>>(xs, x0s, Ccs);
    gemmHL(Ccs, oW0s, 512,  ob0, nullptr, 0, M1s, 256, MTOK, 512,  1024, 1);
    gemmHL(M1s, oW1s, 1024, ob1, nullptr, 0, M2s, 512, MTOK, 1024, 512,  1);
    gemmHL(M2s, oW2s, 1000, ob2, out, 1000, nullptr, 0, MTOK, 1000, 1024, 0);
}